// round 1
// baseline (speedup 1.0000x reference)
#include <cuda_runtime.h>
#include <float.h>

#define BATCH 32
#define PTS   1024
#define NPT   (BATCH*PTS)     // 32768
#define KNN   20
#define EDGES (NPT*KNN)       // 655360
#define STATS_BLOCKS 512
#define EDGES_PER_BLOCK (EDGES/STATS_BLOCKS)  // 1280

// ---------------- scratch (static device globals; no allocation) ----------------
__device__ float g_dist[(size_t)BATCH*PTS*PTS];   // 128 MB, reused by both knn rounds
__device__ int   g_idx[NPT*KNN];
__device__ float g_u1[NPT*64];
__device__ float g_v1[NPT*64];
__device__ float g_x1[NPT*64];
__device__ float g_n2[NPT];
__device__ float g_part[STATS_BLOCKS*128];
__device__ float g_scale[64];
__device__ float g_shift[64];
__device__ float g_Wcat[64*256];
__device__ float g_bcat[256];
__device__ float g_uv2[NPT*256];
__device__ float g_x2[NPT*128];
__device__ float g_h[NPT*128];

// ---------------- knn1: pairwise dist in 3D (bitwise-matching formula) ----------
__global__ __launch_bounds__(1024) void dist3_kernel(const float* __restrict__ pos) {
    unsigned bi = blockIdx.x;            // (b,i) flat: 32768 blocks
    int j = threadIdx.x;
    int i = bi & (PTS - 1);
    int b = bi >> 10;
    const float* pi = pos + (size_t)(b * PTS + i) * 3;
    const float* pj = pos + (size_t)(b * PTS + j) * 3;
    float a0 = pi[0], a1 = pi[1], a2 = pi[2];
    float c0 = pj[0], c1 = pj[1], c2 = pj[2];
    float d2i = __fadd_rn(__fadd_rn(__fmul_rn(a0,a0), __fmul_rn(a1,a1)), __fmul_rn(a2,a2));
    float d2j = __fadd_rn(__fadd_rn(__fmul_rn(c0,c0), __fmul_rn(c1,c1)), __fmul_rn(c2,c2));
    float dot = __fadd_rn(__fadd_rn(__fmul_rn(a0,c0), __fmul_rn(a1,c1)), __fmul_rn(a2,c2));
    g_dist[((size_t)bi << 10) + j] = __fsub_rn(__fadd_rn(d2i, d2j), __fmul_rn(2.0f, dot));
}

// ---------------- top-20 per row, warp-cooperative, (val, idx) lexicographic ----
__device__ __forceinline__ bool kless(float v, int i, float w, int k) {
    return v < w || (v == w && i < k);
}

__global__ __launch_bounds__(256) void topk_kernel() {
    int warp = (blockIdx.x * blockDim.x + threadIdx.x) >> 5;
    int lane = threadIdx.x & 31;
    if (warp >= NPT) return;
    const float* row = g_dist + ((size_t)warp << 10);

    float vals[KNN];
    int   ids[KNN];
#pragma unroll
    for (int t = 0; t < KNN; t++) { vals[t] = FLT_MAX; ids[t] = 0x7fffffff; }

    // streaming insertion into per-lane ascending top-20 (static reg indices only)
    for (int j = lane; j < PTS; j += 32) {
        float v = row[j];
        if (kless(v, j, vals[KNN-1], ids[KNN-1])) {
            int pos = KNN - 1;
#pragma unroll
            for (int t = KNN - 2; t >= 0; t--)
                if (kless(v, j, vals[t], ids[t])) pos = t;
#pragma unroll
            for (int t = KNN - 1; t >= 0; t--) {
                if (t > pos)       { vals[t] = vals[t-1]; ids[t] = ids[t-1]; }
                else if (t == pos) { vals[t] = v;         ids[t] = j;        }
            }
        }
    }

    // 20 rounds of warp arg-min merge (pop from head keeps indices static)
    for (int r = 0; r < KNN; r++) {
        float cv = vals[0]; int ci = ids[0];
#pragma unroll
        for (int o = 16; o > 0; o >>= 1) {
            float ov = __shfl_xor_sync(0xffffffffu, cv, o);
            int   oi = __shfl_xor_sync(0xffffffffu, ci, o);
            if (kless(ov, oi, cv, ci)) { cv = ov; ci = oi; }
        }
        if (lane == 0) g_idx[warp * KNN + r] = ci;
        if (ids[0] == ci && vals[0] == cv) {
#pragma unroll
            for (int t = 0; t < KNN - 1; t++) { vals[t] = vals[t+1]; ids[t] = ids[t+1]; }
            vals[KNN-1] = FLT_MAX; ids[KNN-1] = 0x7fffffff;
        }
    }
}

// ---------------- EdgeConv1 per-point precompute: u = x@(A-B)+b1a, v = x@B ------
__global__ __launch_bounds__(256) void ec1_pre_kernel(
    const float* __restrict__ pos, const float* __restrict__ W1a,
    const float* __restrict__ b1a) {
    int t = blockIdx.x * 256 + threadIdx.x;     // NPT*64 threads
    int c = t & 63;
    int p = t >> 6;
    float x0 = pos[p*3], x1 = pos[p*3+1], x2 = pos[p*3+2];
    float a  = x0 * W1a[c]       + x1 * W1a[64 + c]  + x2 * W1a[128 + c];
    float bb = x0 * W1a[192 + c] + x1 * W1a[256 + c] + x2 * W1a[320 + c];
    g_u1[t] = a - bb + b1a[c];
    g_v1[t] = bb;
}

// ---------------- BN stats over all edges (deterministic 2-level reduce) --------
__global__ __launch_bounds__(256) void ec1_stats_kernel() {
    int c  = threadIdx.x & 63;
    int el = threadIdx.x >> 6;   // 0..3
    float s = 0.f, s2 = 0.f;
    int e0 = blockIdx.x * EDGES_PER_BLOCK;
    for (int e = e0 + el; e < e0 + EDGES_PER_BLOCK; e += 4) {
        int i = e / KNN, k = e - i * KNN;
        int j = ((i >> 10) << 10) + g_idx[i * KNN + k];
        float h = g_u1[i * 64 + c] + g_v1[j * 64 + c];
        s += h;
        s2 = fmaf(h, h, s2);
    }
    __shared__ float sh[2][4][64];
    sh[0][el][c] = s; sh[1][el][c] = s2;
    __syncthreads();
    if (el == 0) {
        float ts = sh[0][0][c] + sh[0][1][c] + sh[0][2][c] + sh[0][3][c];
        float t2 = sh[1][0][c] + sh[1][1][c] + sh[1][2][c] + sh[1][3][c];
        g_part[blockIdx.x * 128 + c]      = ts;
        g_part[blockIdx.x * 128 + 64 + c] = t2;
    }
}

__global__ void ec1_bn_kernel(const float* __restrict__ g1, const float* __restrict__ be1) {
    int c = threadIdx.x;  // 64
    float s = 0.f, s2 = 0.f;
    for (int b = 0; b < STATS_BLOCKS; b++) {
        s  += g_part[b * 128 + c];
        s2 += g_part[b * 128 + 64 + c];
    }
    float n   = (float)EDGES;
    float mu  = s / n;
    float var = s2 / n - mu * mu;
    float sc  = g1[c] * rsqrtf(var + 1e-5f);
    g_scale[c] = sc;
    g_shift[c] = be1[c] - mu * sc;
}

// ---------------- EdgeConv1 apply: BN->ReLU->64x64 GEMV, max over K -------------
__global__ __launch_bounds__(256) void ec1_apply_kernel(
    const float* __restrict__ W1b, const float* __restrict__ b1b) {
    int pt = threadIdx.x >> 6;     // 4 points per block
    int c  = threadIdx.x & 63;
    int i  = blockIdx.x * 4 + pt;

    float w[64];
#pragma unroll
    for (int d = 0; d < 64; d++) w[d] = W1b[d * 64 + c];

    __shared__ float hb[4][64];
    float sc = g_scale[c], sh = g_shift[c];
    float uic = g_u1[i * 64 + c];
    int base = (i >> 10) << 10;
    float bb = b1b[c];
    float acc = -FLT_MAX;

    for (int k = 0; k < KNN; k++) {
        int j = base + g_idx[i * KNN + k];
        float h  = uic + g_v1[j * 64 + c];
        float hn = fmaxf(fmaf(h, sc, sh), 0.0f);
        hb[pt][c] = hn;
        __syncthreads();
        float y = bb;
#pragma unroll
        for (int d = 0; d < 64; d += 4) {
            float4 h4 = *(const float4*)&hb[pt][d];
            y = fmaf(h4.x, w[d],   y);
            y = fmaf(h4.y, w[d+1], y);
            y = fmaf(h4.z, w[d+2], y);
            y = fmaf(h4.w, w[d+3], y);
        }
        acc = fmaxf(acc, y);
        __syncthreads();
    }
    g_x1[i * 64 + c] = acc;
}

// ---------------- knn2 prep: squared norms of x1 ---------------------------------
__global__ void n2_kernel() {
    int p = blockIdx.x * blockDim.x + threadIdx.x;
    const float* x = g_x1 + (size_t)p * 64;
    float s = 0.f;
    for (int d = 0; d < 64; d++) s = __fadd_rn(s, __fmul_rn(x[d], x[d]));
    g_n2[p] = s;
}

// ---------------- knn2: 64-d Gram -> dist, 64x64 tile / 4x4 microtile ------------
__global__ __launch_bounds__(256) void gram_kernel() {
    int b  = blockIdx.z;
    int i0 = blockIdx.y << 6;
    int j0 = blockIdx.x << 6;
    const float* xb = g_x1 + ((size_t)b << 10) * 64;

    __shared__ float As[16][68];
    __shared__ float Bs[16][68];

    int tx = threadIdx.x & 15, ty = threadIdx.x >> 4;
    float acc[4][4];
#pragma unroll
    for (int r = 0; r < 4; r++)
#pragma unroll
        for (int s = 0; s < 4; s++) acc[r][s] = 0.f;

    int kk = threadIdx.x & 15;
    int rb = threadIdx.x >> 4;
    for (int k0 = 0; k0 < 64; k0 += 16) {
#pragma unroll
        for (int rr = 0; rr < 64; rr += 16) {
            As[kk][rb + rr] = xb[(i0 + rb + rr) * 64 + k0 + kk];
            Bs[kk][rb + rr] = xb[(j0 + rb + rr) * 64 + k0 + kk];
        }
        __syncthreads();
#pragma unroll
        for (int k = 0; k < 16; k++) {
            float4 a4 = *(const float4*)&As[k][ty << 2];
            float4 b4 = *(const float4*)&Bs[k][tx << 2];
            float ar[4] = {a4.x, a4.y, a4.z, a4.w};
            float br[4] = {b4.x, b4.y, b4.z, b4.w};
#pragma unroll
            for (int r = 0; r < 4; r++)
#pragma unroll
                for (int s = 0; s < 4; s++) acc[r][s] = fmaf(ar[r], br[s], acc[r][s]);
        }
        __syncthreads();
    }

    float nj[4];
#pragma unroll
    for (int s = 0; s < 4; s++) nj[s] = g_n2[(b << 10) + j0 + (tx << 2) + s];
#pragma unroll
    for (int r = 0; r < 4; r++) {
        int i = i0 + (ty << 2) + r;
        float ni = g_n2[(b << 10) + i];
        float4 o;
        o.x = __fsub_rn(__fadd_rn(ni, nj[0]), __fmul_rn(2.0f, acc[r][0]));
        o.y = __fsub_rn(__fadd_rn(ni, nj[1]), __fmul_rn(2.0f, acc[r][1]));
        o.z = __fsub_rn(__fadd_rn(ni, nj[2]), __fmul_rn(2.0f, acc[r][2]));
        o.w = __fsub_rn(__fadd_rn(ni, nj[3]), __fmul_rn(2.0f, acc[r][3]));
        *(float4*)&g_dist[((size_t)b << 20) + ((size_t)i << 10) + j0 + (tx << 2)] = o;
    }
}

// ---------------- EdgeConv2 weights: Wcat = [A-B | B], bcat = [b2 | 0] ------------
__global__ void prep_wcat_kernel(const float* __restrict__ W2, const float* __restrict__ b2) {
    int t = blockIdx.x * 256 + threadIdx.x;   // 64*256 threads
    int d = t >> 8;
    int c = t & 255;
    float val = (c < 128) ? (W2[d * 128 + c] - W2[(d + 64) * 128 + c])
                          : W2[(d + 64) * 128 + (c - 128)];
    g_Wcat[d * 256 + c] = val;
    if (d == 0) g_bcat[c] = (c < 128) ? b2[c] : 0.0f;
}

// ---------------- generic persistent GEMV: Y[p] = X[p]@W (+bias) (+=Y) -----------
template <int KC, int C, bool ACC, bool HASB>
__device__ __forceinline__ void gemm_body(
    const float* __restrict__ X, int ldx,
    const float* __restrict__ W, const float* __restrict__ bias,
    float* __restrict__ Y, int ldy, int ppb) {
    int c = threadIdx.x;   // blockDim == C
    float w[KC];
#pragma unroll
    for (int d = 0; d < KC; d++) w[d] = W[d * C + c];
    __shared__ float xs[KC];
    float bb = HASB ? bias[c] : 0.0f;
    int p0 = blockIdx.x * ppb;
    for (int p = p0; p < p0 + ppb; p++) {
        if (c < KC) xs[c] = X[(size_t)p * ldx + c];
        __syncthreads();
        float y = bb;
#pragma unroll
        for (int d = 0; d < KC; d += 4) {
            float4 x4 = *(const float4*)&xs[d];
            y = fmaf(x4.x, w[d],   y);
            y = fmaf(x4.y, w[d+1], y);
            y = fmaf(x4.z, w[d+2], y);
            y = fmaf(x4.w, w[d+3], y);
        }
        if (ACC) y += Y[(size_t)p * ldy + c];
        Y[(size_t)p * ldy + c] = y;
        __syncthreads();
    }
}

__global__ __launch_bounds__(256) void ec2_pre_kernel() {
    gemm_body<64, 256, false, true>(g_x1, 64, g_Wcat, g_bcat, g_uv2, 256, 128);
}
__global__ __launch_bounds__(128) void fin_a_kernel(const float* __restrict__ Wl) {
    gemm_body<64, 128, false, false>(g_x1, 64, Wl, nullptr, g_h, 128, 128);
}
__global__ __launch_bounds__(128) void fin_b_kernel(const float* __restrict__ Wl) {
    gemm_body<64, 128, true, false>(g_x2, 128, Wl + 64 * 128, nullptr, g_h, 128, 128);
}
__global__ __launch_bounds__(128) void fin_c_kernel(const float* __restrict__ Wl) {
    gemm_body<64, 128, true, false>(g_x2 + 64, 128, Wl + 128 * 128, nullptr, g_h, 128, 128);
}

// ---------------- EdgeConv2 combine: x2 = u2 + max_k v2[nbr] ---------------------
__global__ __launch_bounds__(256) void ec2_combine_kernel() {
    int t = blockIdx.x * 256 + threadIdx.x;   // NPT*128 threads
    int c = t & 127;
    int i = t >> 7;
    int base = (i >> 10) << 10;
    float m = -FLT_MAX;
    for (int k = 0; k < KNN; k++) {
        int j = base + g_idx[i * KNN + k];
        m = fmaxf(m, g_uv2[j * 256 + 128 + c]);
    }
    g_x2[i * 128 + c] = g_uv2[i * 256 + c] + m;
}

// ---------------- global max pool over points per cloud --------------------------
__global__ void pool_kernel(const float* __restrict__ bl, float* __restrict__ out) {
    int b = blockIdx.x;     // 32
    int c = threadIdx.x;    // 128
    const float* hp = g_h + ((size_t)(b << 10)) * 128 + c;
    float m = -FLT_MAX;
    for (int p = 0; p < PTS; p++) m = fmaxf(m, hp[(size_t)p * 128]);
    out[b * 128 + c] = m + bl[c];
}

// ---------------- launch --------------------------------------------------------
extern "C" void kernel_launch(void* const* d_in, const int* in_sizes, int n_in,
                              void* d_out, int out_size) {
    const float* pos = (const float*)d_in[0];
    const float* W1a = (const float*)d_in[1];
    const float* b1a = (const float*)d_in[2];
    const float* g1  = (const float*)d_in[3];
    const float* be1 = (const float*)d_in[4];
    const float* W1b = (const float*)d_in[5];
    const float* b1b = (const float*)d_in[6];
    const float* W2  = (const float*)d_in[7];
    const float* b2  = (const float*)d_in[8];
    const float* Wl  = (const float*)d_in[9];
    const float* bl  = (const float*)d_in[10];
    float* out = (float*)d_out;

    // knn on pos
    dist3_kernel<<<NPT, 1024>>>(pos);
    topk_kernel<<<NPT / 8, 256>>>();

    // EdgeConv1
    ec1_pre_kernel<<<NPT * 64 / 256, 256>>>(pos, W1a, b1a);
    ec1_stats_kernel<<<STATS_BLOCKS, 256>>>();
    ec1_bn_kernel<<<1, 64>>>(g1, be1);
    ec1_apply_kernel<<<NPT / 4, 256>>>(W1b, b1b);

    // knn on x1
    n2_kernel<<<NPT / 256, 256>>>();
    gram_kernel<<<dim3(16, 16, BATCH), 256>>>();
    topk_kernel<<<NPT / 8, 256>>>();

    // EdgeConv2
    prep_wcat_kernel<<<64, 256>>>(W2, b2);
    ec2_pre_kernel<<<256, 256>>>();
    ec2_combine_kernel<<<NPT * 128 / 256, 256>>>();

    // final linear (3 K-chunks of 64) + pool
    fin_a_kernel<<<256, 128>>>(Wl);
    fin_b_kernel<<<256, 128>>>(Wl);
    fin_c_kernel<<<256, 128>>>(Wl);
    pool_kernel<<<BATCH, 128>>>(bl, out);
}

// round 2
// speedup vs baseline: 1.0940x; 1.0940x over previous
#include <cuda_runtime.h>
#include <float.h>

#define BATCH 32
#define PTS   1024
#define NPT   (BATCH*PTS)     // 32768
#define KNN   20
#define EDGES (NPT*KNN)       // 655360
#define STATS_BLOCKS 512
#define EDGES_PER_BLOCK (EDGES/STATS_BLOCKS)  // 1280

// ---------------- scratch (static device globals; no allocation) ----------------
__device__ float g_dist[(size_t)BATCH*PTS*PTS];   // 128 MB (knn2 only now)
__device__ int   g_idx[NPT*KNN];
__device__ float g_u1[NPT*64];
__device__ float g_v1[NPT*64];
__device__ float g_x1[NPT*64];
__device__ float g_n2[NPT];
__device__ float g_part[STATS_BLOCKS*128];
__device__ float g_scale[64];
__device__ float g_shift[64];
__device__ float g_Wcat[64*256];
__device__ float g_bcat[256];
__device__ float g_uv2[NPT*256];
__device__ float g_x2[NPT*128];
__device__ float g_h[NPT*128];

// ---------------- shared top-k machinery (lexicographic (val,idx)) ---------------
__device__ __forceinline__ bool kless(float v, int i, float w, int k) {
    return v < w || (v == w && i < k);
}

// per-lane sorted insertion of (v, j) into ascending top-KNN
__device__ __forceinline__ void kinsert(float v, int j, float (&vals)[KNN], int (&ids)[KNN]) {
    if (kless(v, j, vals[KNN-1], ids[KNN-1])) {
        int pos = KNN - 1;
#pragma unroll
        for (int t = KNN - 2; t >= 0; t--)
            if (kless(v, j, vals[t], ids[t])) pos = t;
#pragma unroll
        for (int t = KNN - 1; t >= 0; t--) {
            if (t > pos)       { vals[t] = vals[t-1]; ids[t] = ids[t-1]; }
            else if (t == pos) { vals[t] = v;         ids[t] = j;        }
        }
    }
}

// warp merge of per-lane sorted lists -> write KNN indices for row `row`
__device__ __forceinline__ void kmerge_write(float (&vals)[KNN], int (&ids)[KNN], int row) {
    int lane = threadIdx.x & 31;
    for (int r = 0; r < KNN; r++) {
        float cv = vals[0]; int ci = ids[0];
#pragma unroll
        for (int o = 16; o > 0; o >>= 1) {
            float ov = __shfl_xor_sync(0xffffffffu, cv, o);
            int   oi = __shfl_xor_sync(0xffffffffu, ci, o);
            if (kless(ov, oi, cv, ci)) { cv = ov; ci = oi; }
        }
        if (lane == 0) g_idx[row * KNN + r] = ci;
        if (ids[0] == ci && vals[0] == cv) {
#pragma unroll
            for (int t = 0; t < KNN - 1; t++) { vals[t] = vals[t+1]; ids[t] = ids[t+1]; }
            vals[KNN-1] = FLT_MAX; ids[KNN-1] = 0x7fffffff;
        }
    }
}

// ---------------- knn1 fused: dist-on-the-fly (exact op order) + top-20 ---------
__global__ __launch_bounds__(256) void knn1_kernel(const float* __restrict__ pos) {
    __shared__ float4 sp[PTS];   // 16 KB: {x,y,z,d2}
    int cloud  = blockIdx.x >> 7;      // 128 blocks per cloud, 8 rows per block
    int rowblk = blockIdx.x & 127;
    const float* pb = pos + (size_t)cloud * PTS * 3;
    for (int p = threadIdx.x; p < PTS; p += 256) {
        float x = pb[p*3], y = pb[p*3+1], z = pb[p*3+2];
        float d2 = __fadd_rn(__fadd_rn(__fmul_rn(x,x), __fmul_rn(y,y)), __fmul_rn(z,z));
        sp[p] = make_float4(x, y, z, d2);
    }
    __syncthreads();

    int warp = threadIdx.x >> 5, lane = threadIdx.x & 31;
    int il = rowblk * 8 + warp;
    float4 q = sp[il];

    float vals[KNN]; int ids[KNN];
#pragma unroll
    for (int t = 0; t < KNN; t++) { vals[t] = FLT_MAX; ids[t] = 0x7fffffff; }

    for (int t = 0; t < 32; t++) {
        int j = t * 32 + lane;
        float4 p = sp[j];
        float dot = __fadd_rn(__fadd_rn(__fmul_rn(q.x,p.x), __fmul_rn(q.y,p.y)), __fmul_rn(q.z,p.z));
        float v = __fsub_rn(__fadd_rn(q.w, p.w), __fmul_rn(2.0f, dot));
        kinsert(v, j, vals, ids);
    }
    kmerge_write(vals, ids, cloud * PTS + il);
}

// ---------------- knn2 top-k (reads g_dist) --------------------------------------
__global__ __launch_bounds__(256) void topk_kernel() {
    int warp = (blockIdx.x * blockDim.x + threadIdx.x) >> 5;
    int lane = threadIdx.x & 31;
    if (warp >= NPT) return;
    const float* row = g_dist + ((size_t)warp << 10);

    float vals[KNN]; int ids[KNN];
#pragma unroll
    for (int t = 0; t < KNN; t++) { vals[t] = FLT_MAX; ids[t] = 0x7fffffff; }
    for (int j = lane; j < PTS; j += 32) kinsert(row[j], j, vals, ids);
    kmerge_write(vals, ids, warp);
}

// ---------------- EdgeConv1 per-point precompute: u = x@(A-B)+b1a, v = x@B ------
__global__ __launch_bounds__(256) void ec1_pre_kernel(
    const float* __restrict__ pos, const float* __restrict__ W1a,
    const float* __restrict__ b1a) {
    int t = blockIdx.x * 256 + threadIdx.x;     // NPT*64 threads
    int c = t & 63;
    int p = t >> 6;
    float x0 = pos[p*3], x1 = pos[p*3+1], x2 = pos[p*3+2];
    float a  = x0 * W1a[c]       + x1 * W1a[64 + c]  + x2 * W1a[128 + c];
    float bb = x0 * W1a[192 + c] + x1 * W1a[256 + c] + x2 * W1a[320 + c];
    g_u1[t] = a - bb + b1a[c];
    g_v1[t] = bb;
}

// ---------------- BN stats over all edges (deterministic 2-level reduce) --------
__global__ __launch_bounds__(256) void ec1_stats_kernel() {
    int c  = threadIdx.x & 63;
    int el = threadIdx.x >> 6;   // 0..3
    float s = 0.f, s2 = 0.f;
    int e0 = blockIdx.x * EDGES_PER_BLOCK;
    for (int e = e0 + el; e < e0 + EDGES_PER_BLOCK; e += 4) {
        int i = e / KNN, k = e - i * KNN;
        int j = ((i >> 10) << 10) + g_idx[i * KNN + k];
        float h = g_u1[i * 64 + c] + g_v1[j * 64 + c];
        s += h;
        s2 = fmaf(h, h, s2);
    }
    __shared__ float sh[2][4][64];
    sh[0][el][c] = s; sh[1][el][c] = s2;
    __syncthreads();
    if (el == 0) {
        float ts = sh[0][0][c] + sh[0][1][c] + sh[0][2][c] + sh[0][3][c];
        float t2 = sh[1][0][c] + sh[1][1][c] + sh[1][2][c] + sh[1][3][c];
        g_part[blockIdx.x * 128 + c]      = ts;
        g_part[blockIdx.x * 128 + 64 + c] = t2;
    }
}

__global__ void ec1_bn_kernel(const float* __restrict__ g1, const float* __restrict__ be1) {
    int c = threadIdx.x;  // 64
    float s = 0.f, s2 = 0.f;
    for (int b = 0; b < STATS_BLOCKS; b++) {
        s  += g_part[b * 128 + c];
        s2 += g_part[b * 128 + 64 + c];
    }
    float n   = (float)EDGES;
    float mu  = s / n;
    float var = s2 / n - mu * mu;
    float sc  = g1[c] * rsqrtf(var + 1e-5f);
    g_scale[c] = sc;
    g_shift[c] = be1[c] - mu * sc;
}

// ---------------- fold BN affine into u,v in place -------------------------------
__global__ __launch_bounds__(256) void ec1_scale_kernel() {
    int t = blockIdx.x * 256 + threadIdx.x;   // NPT*64
    int c = t & 63;
    g_u1[t] = fmaf(g_u1[t], g_scale[c], g_shift[c]);
    g_v1[t] = g_v1[t] * g_scale[c];
}

// ---------------- EdgeConv1 apply: relu(a_i+b_j) @ W1b, max over K ---------------
__global__ __launch_bounds__(256) void ec1_apply_kernel(
    const float* __restrict__ W1b, const float* __restrict__ b1b) {
    int pt = threadIdx.x >> 6;     // 4 points per block
    int c  = threadIdx.x & 63;
    int i  = blockIdx.x * 4 + pt;

    float w[64];
#pragma unroll
    for (int d = 0; d < 64; d++) w[d] = W1b[d * 64 + c];

    __shared__ float hb[2][4][64];
    float a   = g_u1[i * 64 + c];
    int  base = (i >> 10) << 10;
    float bb  = b1b[c];
    float acc = -FLT_MAX;

    // prologue: k = 0
    {
        int j = base + g_idx[i * KNN];
        hb[0][pt][c] = fmaxf(a + g_v1[j * 64 + c], 0.0f);
    }
    __syncthreads();

    for (int k = 0; k < KNN; k++) {
        int cur = k & 1;
        if (k + 1 < KNN) {
            int j2 = base + g_idx[i * KNN + k + 1];
            hb[cur ^ 1][pt][c] = fmaxf(a + g_v1[j2 * 64 + c], 0.0f);
        }
        float y0 = bb, y1 = 0.f, y2 = 0.f, y3 = 0.f;
#pragma unroll
        for (int d = 0; d < 64; d += 16) {
            float4 p0 = *(const float4*)&hb[cur][pt][d];
            float4 p1 = *(const float4*)&hb[cur][pt][d + 4];
            float4 p2 = *(const float4*)&hb[cur][pt][d + 8];
            float4 p3 = *(const float4*)&hb[cur][pt][d + 12];
            y0 = fmaf(p0.x, w[d],    y0); y0 = fmaf(p0.y, w[d+1],  y0);
            y0 = fmaf(p0.z, w[d+2],  y0); y0 = fmaf(p0.w, w[d+3],  y0);
            y1 = fmaf(p1.x, w[d+4],  y1); y1 = fmaf(p1.y, w[d+5],  y1);
            y1 = fmaf(p1.z, w[d+6],  y1); y1 = fmaf(p1.w, w[d+7],  y1);
            y2 = fmaf(p2.x, w[d+8],  y2); y2 = fmaf(p2.y, w[d+9],  y2);
            y2 = fmaf(p2.z, w[d+10], y2); y2 = fmaf(p2.w, w[d+11], y2);
            y3 = fmaf(p3.x, w[d+12], y3); y3 = fmaf(p3.y, w[d+13], y3);
            y3 = fmaf(p3.z, w[d+14], y3); y3 = fmaf(p3.w, w[d+15], y3);
        }
        acc = fmaxf(acc, (y0 + y1) + (y2 + y3));
        __syncthreads();
    }
    g_x1[i * 64 + c] = acc;
}

// ---------------- knn2 prep: squared norms of x1 ---------------------------------
__global__ void n2_kernel() {
    int p = blockIdx.x * blockDim.x + threadIdx.x;
    const float* x = g_x1 + (size_t)p * 64;
    float s = 0.f;
    for (int d = 0; d < 64; d++) s = __fadd_rn(s, __fmul_rn(x[d], x[d]));
    g_n2[p] = s;
}

// ---------------- knn2: Gram GEMM, 128x128 tile / 8x8 microtile ------------------
__global__ __launch_bounds__(256) void gram_kernel() {
    int b  = blockIdx.z;
    int i0 = blockIdx.y << 7;
    int j0 = blockIdx.x << 7;
    const float* xb = g_x1 + ((size_t)b << 10) * 64;

    __shared__ float As[16][132];
    __shared__ float Bs[16][132];

    int tid = threadIdx.x;
    int tx = tid & 15, ty = tid >> 4;          // 16x16 thread grid, 8x8 each
    int lr = tid >> 2, lc4 = tid & 3;          // loader: row 0..63, float4 col 0..3

    float acc[8][8];
#pragma unroll
    for (int r = 0; r < 8; r++)
#pragma unroll
        for (int s = 0; s < 8; s++) acc[r][s] = 0.f;

    for (int k0 = 0; k0 < 64; k0 += 16) {
#pragma unroll
        for (int half = 0; half < 2; half++) {
            int r = lr + half * 64;
            float4 av = *(const float4*)&xb[(i0 + r) * 64 + k0 + lc4 * 4];
            float4 bv = *(const float4*)&xb[(j0 + r) * 64 + k0 + lc4 * 4];
            As[lc4*4+0][r] = av.x; As[lc4*4+1][r] = av.y;
            As[lc4*4+2][r] = av.z; As[lc4*4+3][r] = av.w;
            Bs[lc4*4+0][r] = bv.x; Bs[lc4*4+1][r] = bv.y;
            Bs[lc4*4+2][r] = bv.z; Bs[lc4*4+3][r] = bv.w;
        }
        __syncthreads();
#pragma unroll
        for (int k = 0; k < 16; k++) {
            float4 a0 = *(const float4*)&As[k][ty << 3];
            float4 a1 = *(const float4*)&As[k][(ty << 3) + 4];
            float4 b0 = *(const float4*)&Bs[k][tx << 3];
            float4 b1 = *(const float4*)&Bs[k][(tx << 3) + 4];
            float ar[8] = {a0.x, a0.y, a0.z, a0.w, a1.x, a1.y, a1.z, a1.w};
            float br[8] = {b0.x, b0.y, b0.z, b0.w, b1.x, b1.y, b1.z, b1.w};
#pragma unroll
            for (int r = 0; r < 8; r++)
#pragma unroll
                for (int s = 0; s < 8; s++) acc[r][s] = fmaf(ar[r], br[s], acc[r][s]);
        }
        __syncthreads();
    }

    float nj[8];
#pragma unroll
    for (int s = 0; s < 8; s++) nj[s] = g_n2[(b << 10) + j0 + (tx << 3) + s];
#pragma unroll
    for (int r = 0; r < 8; r++) {
        int i = i0 + (ty << 3) + r;
        float ni = g_n2[(b << 10) + i];
        float4 o0, o1;
        o0.x = __fsub_rn(__fadd_rn(ni, nj[0]), __fmul_rn(2.0f, acc[r][0]));
        o0.y = __fsub_rn(__fadd_rn(ni, nj[1]), __fmul_rn(2.0f, acc[r][1]));
        o0.z = __fsub_rn(__fadd_rn(ni, nj[2]), __fmul_rn(2.0f, acc[r][2]));
        o0.w = __fsub_rn(__fadd_rn(ni, nj[3]), __fmul_rn(2.0f, acc[r][3]));
        o1.x = __fsub_rn(__fadd_rn(ni, nj[4]), __fmul_rn(2.0f, acc[r][4]));
        o1.y = __fsub_rn(__fadd_rn(ni, nj[5]), __fmul_rn(2.0f, acc[r][5]));
        o1.z = __fsub_rn(__fadd_rn(ni, nj[6]), __fmul_rn(2.0f, acc[r][6]));
        o1.w = __fsub_rn(__fadd_rn(ni, nj[7]), __fmul_rn(2.0f, acc[r][7]));
        size_t off = ((size_t)b << 20) + ((size_t)i << 10) + j0 + (tx << 3);
        *(float4*)&g_dist[off]     = o0;
        *(float4*)&g_dist[off + 4] = o1;
    }
}

// ---------------- EdgeConv2 weights: Wcat = [A-B | B], bcat = [b2 | 0] ------------
__global__ void prep_wcat_kernel(const float* __restrict__ W2, const float* __restrict__ b2) {
    int t = blockIdx.x * 256 + threadIdx.x;   // 64*256 threads
    int d = t >> 8;
    int c = t & 255;
    float val = (c < 128) ? (W2[d * 128 + c] - W2[(d + 64) * 128 + c])
                          : W2[(d + 64) * 128 + (c - 128)];
    g_Wcat[d * 256 + c] = val;
    if (d == 0) g_bcat[c] = (c < 128) ? b2[c] : 0.0f;
}

// ---------------- generic persistent GEMV: Y[p] = X[p]@W (+bias) (+=Y) -----------
template <int KC, int C, bool ACC, bool HASB>
__device__ __forceinline__ void gemm_body(
    const float* __restrict__ X, int ldx,
    const float* __restrict__ W, const float* __restrict__ bias,
    float* __restrict__ Y, int ldy, int ppb) {
    int c = threadIdx.x;   // blockDim == C
    float w[KC];
#pragma unroll
    for (int d = 0; d < KC; d++) w[d] = W[d * C + c];
    __shared__ float xs[KC];
    float bb = HASB ? bias[c] : 0.0f;
    int p0 = blockIdx.x * ppb;
    for (int p = p0; p < p0 + ppb; p++) {
        if (c < KC) xs[c] = X[(size_t)p * ldx + c];
        __syncthreads();
        float y = bb;
#pragma unroll
        for (int d = 0; d < KC; d += 4) {
            float4 x4 = *(const float4*)&xs[d];
            y = fmaf(x4.x, w[d],   y);
            y = fmaf(x4.y, w[d+1], y);
            y = fmaf(x4.z, w[d+2], y);
            y = fmaf(x4.w, w[d+3], y);
        }
        if (ACC) y += Y[(size_t)p * ldy + c];
        Y[(size_t)p * ldy + c] = y;
        __syncthreads();
    }
}

__global__ __launch_bounds__(256) void ec2_pre_kernel() {
    gemm_body<64, 256, false, true>(g_x1, 64, g_Wcat, g_bcat, g_uv2, 256, 128);
}
__global__ __launch_bounds__(128) void fin_a_kernel(const float* __restrict__ Wl) {
    gemm_body<64, 128, false, false>(g_x1, 64, Wl, nullptr, g_h, 128, 128);
}
__global__ __launch_bounds__(128) void fin_b_kernel(const float* __restrict__ Wl) {
    gemm_body<64, 128, true, false>(g_x2, 128, Wl + 64 * 128, nullptr, g_h, 128, 128);
}
__global__ __launch_bounds__(128) void fin_c_kernel(const float* __restrict__ Wl) {
    gemm_body<64, 128, true, false>(g_x2 + 64, 128, Wl + 128 * 128, nullptr, g_h, 128, 128);
}

// ---------------- EdgeConv2 combine: x2 = u2 + max_k v2[nbr] ---------------------
__global__ __launch_bounds__(256) void ec2_combine_kernel() {
    int t = blockIdx.x * 256 + threadIdx.x;   // NPT*128 threads
    int c = t & 127;
    int i = t >> 7;
    int base = (i >> 10) << 10;
    float m = -FLT_MAX;
    for (int k = 0; k < KNN; k++) {
        int j = base + g_idx[i * KNN + k];
        m = fmaxf(m, g_uv2[j * 256 + 128 + c]);
    }
    g_x2[i * 128 + c] = g_uv2[i * 256 + c] + m;
}

// ---------------- two-stage global max pool --------------------------------------
__global__ void pool1_kernel() {
    int blk = blockIdx.x;     // 256: cloud*8 + seg
    int c = threadIdx.x;      // 128
    int cloud = blk >> 3, seg = blk & 7;
    const float* hp = g_h + ((size_t)(cloud * 1024 + seg * 128)) * 128 + c;
    float m = -FLT_MAX;
    for (int p = 0; p < 128; p++) m = fmaxf(m, hp[(size_t)p * 128]);
    g_part[blk * 128 + c] = m;
}
__global__ void pool2_kernel(const float* __restrict__ bl, float* __restrict__ out) {
    int b = blockIdx.x;       // 32
    int c = threadIdx.x;      // 128
    float m = -FLT_MAX;
    for (int s = 0; s < 8; s++) m = fmaxf(m, g_part[(b * 8 + s) * 128 + c]);
    out[b * 128 + c] = m + bl[c];
}

// ---------------- launch --------------------------------------------------------
extern "C" void kernel_launch(void* const* d_in, const int* in_sizes, int n_in,
                              void* d_out, int out_size) {
    const float* pos = (const float*)d_in[0];
    const float* W1a = (const float*)d_in[1];
    const float* b1a = (const float*)d_in[2];
    const float* g1  = (const float*)d_in[3];
    const float* be1 = (const float*)d_in[4];
    const float* W1b = (const float*)d_in[5];
    const float* b1b = (const float*)d_in[6];
    const float* W2  = (const float*)d_in[7];
    const float* b2  = (const float*)d_in[8];
    const float* Wl  = (const float*)d_in[9];
    const float* bl  = (const float*)d_in[10];
    float* out = (float*)d_out;

    // knn on pos (fused dist + top-k)
    knn1_kernel<<<4096, 256>>>(pos);

    // EdgeConv1
    ec1_pre_kernel<<<NPT * 64 / 256, 256>>>(pos, W1a, b1a);
    ec1_stats_kernel<<<STATS_BLOCKS, 256>>>();
    ec1_bn_kernel<<<1, 64>>>(g1, be1);
    ec1_scale_kernel<<<NPT * 64 / 256, 256>>>();
    ec1_apply_kernel<<<NPT / 4, 256>>>(W1b, b1b);

    // knn on x1
    n2_kernel<<<NPT / 256, 256>>>();
    gram_kernel<<<dim3(8, 8, BATCH), 256>>>();
    topk_kernel<<<NPT / 8, 256>>>();

    // EdgeConv2
    prep_wcat_kernel<<<64, 256>>>(W2, b2);
    ec2_pre_kernel<<<256, 256>>>();
    ec2_combine_kernel<<<NPT * 128 / 256, 256>>>();

    // final linear (3 K-chunks of 64) + pool
    fin_a_kernel<<<256, 128>>>(Wl);
    fin_b_kernel<<<256, 128>>>(Wl);
    fin_c_kernel<<<256, 128>>>(Wl);
    pool1_kernel<<<256, 128>>>();
    pool2_kernel<<<BATCH, 128>>>(bl, out);
}

// round 3
// speedup vs baseline: 1.3356x; 1.2208x over previous
#include <cuda_runtime.h>
#include <float.h>

#define BATCH 32
#define PTS   1024
#define NPT   (BATCH*PTS)     // 32768
#define KNN   20
#define EDGES (NPT*KNN)       // 655360
#define STATS_BLOCKS 512
#define EDGES_PER_BLOCK (EDGES/STATS_BLOCKS)  // 1280

// ---------------- scratch (static device globals; no allocation) ----------------
__device__ float g_dist[(size_t)BATCH*PTS*PTS];   // 128 MB (knn2 only)
__device__ int   g_idx[NPT*KNN];
__device__ float g_u1[NPT*64];
__device__ float g_v1[NPT*64];
__device__ float g_x1[NPT*64];
__device__ float g_n2[NPT];
__device__ float g_part[STATS_BLOCKS*128];        // stats partials, later pool partials
__device__ float g_scale[64];
__device__ float g_shift[64];
__device__ float g_v2[NPT*128];
__device__ float g_m[NPT*128];
__device__ float g_Weff[64*128];
__device__ float g_beff[128];

// ---------------- shared top-k machinery (lexicographic (val,idx)) ---------------
__device__ __forceinline__ bool kless(float v, int i, float w, int k) {
    return v < w || (v == w && i < k);
}

__device__ __forceinline__ void kinsert(float v, int j, float (&vals)[KNN], int (&ids)[KNN]) {
    if (kless(v, j, vals[KNN-1], ids[KNN-1])) {
        int pos = KNN - 1;
#pragma unroll
        for (int t = KNN - 2; t >= 0; t--)
            if (kless(v, j, vals[t], ids[t])) pos = t;
#pragma unroll
        for (int t = KNN - 1; t >= 0; t--) {
            if (t > pos)       { vals[t] = vals[t-1]; ids[t] = ids[t-1]; }
            else if (t == pos) { vals[t] = v;         ids[t] = j;        }
        }
    }
}

__device__ __forceinline__ void kmerge_write(float (&vals)[KNN], int (&ids)[KNN], int row) {
    int lane = threadIdx.x & 31;
    for (int r = 0; r < KNN; r++) {
        float cv = vals[0]; int ci = ids[0];
#pragma unroll
        for (int o = 16; o > 0; o >>= 1) {
            float ov = __shfl_xor_sync(0xffffffffu, cv, o);
            int   oi = __shfl_xor_sync(0xffffffffu, ci, o);
            if (kless(ov, oi, cv, ci)) { cv = ov; ci = oi; }
        }
        if (lane == 0) g_idx[row * KNN + r] = ci;
        if (ids[0] == ci && vals[0] == cv) {
#pragma unroll
            for (int t = 0; t < KNN - 1; t++) { vals[t] = vals[t+1]; ids[t] = ids[t+1]; }
            vals[KNN-1] = FLT_MAX; ids[KNN-1] = 0x7fffffff;
        }
    }
}

// ---------------- knn1 fused: dist-on-the-fly (exact op order) + top-20 ---------
__global__ __launch_bounds__(256) void knn1_kernel(const float* __restrict__ pos) {
    __shared__ float4 sp[PTS];   // 16 KB: {x,y,z,d2}
    int cloud  = blockIdx.x >> 7;
    int rowblk = blockIdx.x & 127;
    const float* pb = pos + (size_t)cloud * PTS * 3;
    for (int p = threadIdx.x; p < PTS; p += 256) {
        float x = pb[p*3], y = pb[p*3+1], z = pb[p*3+2];
        float d2 = __fadd_rn(__fadd_rn(__fmul_rn(x,x), __fmul_rn(y,y)), __fmul_rn(z,z));
        sp[p] = make_float4(x, y, z, d2);
    }
    __syncthreads();

    int warp = threadIdx.x >> 5, lane = threadIdx.x & 31;
    int il = rowblk * 8 + warp;
    float4 q = sp[il];

    float vals[KNN]; int ids[KNN];
#pragma unroll
    for (int t = 0; t < KNN; t++) { vals[t] = FLT_MAX; ids[t] = 0x7fffffff; }

    for (int t = 0; t < 32; t++) {
        int j = t * 32 + lane;
        float4 p = sp[j];
        float dot = __fadd_rn(__fadd_rn(__fmul_rn(q.x,p.x), __fmul_rn(q.y,p.y)), __fmul_rn(q.z,p.z));
        float v = __fsub_rn(__fadd_rn(q.w, p.w), __fmul_rn(2.0f, dot));
        kinsert(v, j, vals, ids);
    }
    kmerge_write(vals, ids, cloud * PTS + il);
}

// ---------------- knn2 top-k (reads g_dist) --------------------------------------
__global__ __launch_bounds__(256) void topk_kernel() {
    int warp = (blockIdx.x * blockDim.x + threadIdx.x) >> 5;
    int lane = threadIdx.x & 31;
    if (warp >= NPT) return;
    const float* row = g_dist + ((size_t)warp << 10);

    float vals[KNN]; int ids[KNN];
#pragma unroll
    for (int t = 0; t < KNN; t++) { vals[t] = FLT_MAX; ids[t] = 0x7fffffff; }
    for (int j = lane; j < PTS; j += 32) kinsert(row[j], j, vals, ids);
    kmerge_write(vals, ids, warp);
}

// ---------------- EdgeConv1 per-point precompute: u = x@(A-B)+b1a, v = x@B ------
__global__ __launch_bounds__(256) void ec1_pre_kernel(
    const float* __restrict__ pos, const float* __restrict__ W1a,
    const float* __restrict__ b1a) {
    int t = blockIdx.x * 256 + threadIdx.x;     // NPT*64 threads
    int c = t & 63;
    int p = t >> 6;
    float x0 = pos[p*3], x1 = pos[p*3+1], x2 = pos[p*3+2];
    float a  = x0 * W1a[c]       + x1 * W1a[64 + c]  + x2 * W1a[128 + c];
    float bb = x0 * W1a[192 + c] + x1 * W1a[256 + c] + x2 * W1a[320 + c];
    g_u1[t] = a - bb + b1a[c];
    g_v1[t] = bb;
}

// ---------------- BN stats over all edges (deterministic 2-level reduce) --------
__global__ __launch_bounds__(256) void ec1_stats_kernel() {
    int c  = threadIdx.x & 63;
    int el = threadIdx.x >> 6;   // 0..3
    float s = 0.f, s2 = 0.f;
    int e0 = blockIdx.x * EDGES_PER_BLOCK;
    for (int e = e0 + el; e < e0 + EDGES_PER_BLOCK; e += 4) {
        int i = e / KNN, k = e - i * KNN;
        int j = ((i >> 10) << 10) + g_idx[i * KNN + k];
        float h = g_u1[i * 64 + c] + g_v1[j * 64 + c];
        s += h;
        s2 = fmaf(h, h, s2);
    }
    __shared__ float sh[2][4][64];
    sh[0][el][c] = s; sh[1][el][c] = s2;
    __syncthreads();
    if (el == 0) {
        float ts = sh[0][0][c] + sh[0][1][c] + sh[0][2][c] + sh[0][3][c];
        float t2 = sh[1][0][c] + sh[1][1][c] + sh[1][2][c] + sh[1][3][c];
        g_part[blockIdx.x * 128 + c]      = ts;
        g_part[blockIdx.x * 128 + 64 + c] = t2;
    }
}

// ---------------- BN finalize (parallel: 8 partial lanes per channel) ------------
__global__ __launch_bounds__(512) void ec1_bn_kernel(
    const float* __restrict__ g1, const float* __restrict__ be1) {
    int c = threadIdx.x & 63;
    int g = threadIdx.x >> 6;    // 0..7
    float s = 0.f, s2 = 0.f;
    for (int b = g; b < STATS_BLOCKS; b += 8) {
        s  += g_part[b * 128 + c];
        s2 += g_part[b * 128 + 64 + c];
    }
    __shared__ float sh[8][64], sh2[8][64];
    sh[g][c] = s; sh2[g][c] = s2;
    __syncthreads();
    if (g == 0) {
        float ts = 0.f, t2 = 0.f;
#pragma unroll
        for (int r = 0; r < 8; r++) { ts += sh[r][c]; t2 += sh2[r][c]; }
        float n   = (float)EDGES;
        float mu  = ts / n;
        float var = t2 / n - mu * mu;
        float sc  = g1[c] * rsqrtf(var + 1e-5f);
        g_scale[c] = sc;
        g_shift[c] = be1[c] - mu * sc;
    }
}

// ---------------- EdgeConv1 apply: stage 20 relu'd edges, then straight GEMV -----
__global__ __launch_bounds__(256) void ec1_apply_kernel(
    const float* __restrict__ W1b, const float* __restrict__ b1b) {
    int pt = threadIdx.x >> 6;     // 4 points per block
    int c  = threadIdx.x & 63;
    int i  = blockIdx.x * 4 + pt;

    float w[64];
#pragma unroll
    for (int d = 0; d < 64; d++) w[d] = W1b[d * 64 + c];

    __shared__ float hb[4][KNN][64];
    float sc  = g_scale[c], shv = g_shift[c];
    float a   = fmaf(g_u1[i * 64 + c], sc, shv);
    int  base = (i >> 10) << 10;

#pragma unroll
    for (int k = 0; k < KNN; k++) {
        int j = base + g_idx[i * KNN + k];
        hb[pt][k][c] = fmaxf(fmaf(g_v1[j * 64 + c], sc, a), 0.0f);
    }
    __syncthreads();

    float bb  = b1b[c];
    float acc = -FLT_MAX;
#pragma unroll
    for (int k = 0; k < KNN; k++) {
        float y0 = bb, y1 = 0.f, y2 = 0.f, y3 = 0.f;
#pragma unroll
        for (int d = 0; d < 64; d += 16) {
            float4 p0 = *(const float4*)&hb[pt][k][d];
            float4 p1 = *(const float4*)&hb[pt][k][d + 4];
            float4 p2 = *(const float4*)&hb[pt][k][d + 8];
            float4 p3 = *(const float4*)&hb[pt][k][d + 12];
            y0 = fmaf(p0.x, w[d],    y0); y0 = fmaf(p0.y, w[d+1],  y0);
            y0 = fmaf(p0.z, w[d+2],  y0); y0 = fmaf(p0.w, w[d+3],  y0);
            y1 = fmaf(p1.x, w[d+4],  y1); y1 = fmaf(p1.y, w[d+5],  y1);
            y1 = fmaf(p1.z, w[d+6],  y1); y1 = fmaf(p1.w, w[d+7],  y1);
            y2 = fmaf(p2.x, w[d+8],  y2); y2 = fmaf(p2.y, w[d+9],  y2);
            y2 = fmaf(p2.z, w[d+10], y2); y2 = fmaf(p2.w, w[d+11], y2);
            y3 = fmaf(p3.x, w[d+12], y3); y3 = fmaf(p3.y, w[d+13], y3);
            y3 = fmaf(p3.z, w[d+14], y3); y3 = fmaf(p3.w, w[d+15], y3);
        }
        acc = fmaxf(acc, (y0 + y1) + (y2 + y3));
    }
    g_x1[i * 64 + c] = acc;
}

// ---------------- knn2 prep: squared norms of x1 ---------------------------------
__global__ void n2_kernel() {
    int p = blockIdx.x * blockDim.x + threadIdx.x;
    const float* x = g_x1 + (size_t)p * 64;
    float s = 0.f;
    for (int d = 0; d < 64; d++) s = __fadd_rn(s, __fmul_rn(x[d], x[d]));
    g_n2[p] = s;
}

// ---------------- knn2: Gram GEMM, 128x128 tile / 8x8 microtile ------------------
__global__ __launch_bounds__(256) void gram_kernel() {
    int b  = blockIdx.z;
    int i0 = blockIdx.y << 7;
    int j0 = blockIdx.x << 7;
    const float* xb = g_x1 + ((size_t)b << 10) * 64;

    __shared__ float As[16][132];
    __shared__ float Bs[16][132];

    int tid = threadIdx.x;
    int tx = tid & 15, ty = tid >> 4;
    int lr = tid >> 2, lc4 = tid & 3;

    float acc[8][8];
#pragma unroll
    for (int r = 0; r < 8; r++)
#pragma unroll
        for (int s = 0; s < 8; s++) acc[r][s] = 0.f;

    for (int k0 = 0; k0 < 64; k0 += 16) {
#pragma unroll
        for (int half = 0; half < 2; half++) {
            int r = lr + half * 64;
            float4 av = *(const float4*)&xb[(i0 + r) * 64 + k0 + lc4 * 4];
            float4 bv = *(const float4*)&xb[(j0 + r) * 64 + k0 + lc4 * 4];
            As[lc4*4+0][r] = av.x; As[lc4*4+1][r] = av.y;
            As[lc4*4+2][r] = av.z; As[lc4*4+3][r] = av.w;
            Bs[lc4*4+0][r] = bv.x; Bs[lc4*4+1][r] = bv.y;
            Bs[lc4*4+2][r] = bv.z; Bs[lc4*4+3][r] = bv.w;
        }
        __syncthreads();
#pragma unroll
        for (int k = 0; k < 16; k++) {
            float4 a0 = *(const float4*)&As[k][ty << 3];
            float4 a1 = *(const float4*)&As[k][(ty << 3) + 4];
            float4 b0 = *(const float4*)&Bs[k][tx << 3];
            float4 b1 = *(const float4*)&Bs[k][(tx << 3) + 4];
            float ar[8] = {a0.x, a0.y, a0.z, a0.w, a1.x, a1.y, a1.z, a1.w};
            float br[8] = {b0.x, b0.y, b0.z, b0.w, b1.x, b1.y, b1.z, b1.w};
#pragma unroll
            for (int r = 0; r < 8; r++)
#pragma unroll
                for (int s = 0; s < 8; s++) acc[r][s] = fmaf(ar[r], br[s], acc[r][s]);
        }
        __syncthreads();
    }

    float nj[8];
#pragma unroll
    for (int s = 0; s < 8; s++) nj[s] = g_n2[(b << 10) + j0 + (tx << 3) + s];
#pragma unroll
    for (int r = 0; r < 8; r++) {
        int i = i0 + (ty << 3) + r;
        float ni = g_n2[(b << 10) + i];
        float4 o0, o1;
        o0.x = __fsub_rn(__fadd_rn(ni, nj[0]), __fmul_rn(2.0f, acc[r][0]));
        o0.y = __fsub_rn(__fadd_rn(ni, nj[1]), __fmul_rn(2.0f, acc[r][1]));
        o0.z = __fsub_rn(__fadd_rn(ni, nj[2]), __fmul_rn(2.0f, acc[r][2]));
        o0.w = __fsub_rn(__fadd_rn(ni, nj[3]), __fmul_rn(2.0f, acc[r][3]));
        o1.x = __fsub_rn(__fadd_rn(ni, nj[4]), __fmul_rn(2.0f, acc[r][4]));
        o1.y = __fsub_rn(__fadd_rn(ni, nj[5]), __fmul_rn(2.0f, acc[r][5]));
        o1.z = __fsub_rn(__fadd_rn(ni, nj[6]), __fmul_rn(2.0f, acc[r][6]));
        o1.w = __fsub_rn(__fadd_rn(ni, nj[7]), __fmul_rn(2.0f, acc[r][7]));
        size_t off = ((size_t)b << 20) + ((size_t)i << 10) + j0 + (tx << 3);
        *(float4*)&g_dist[off]     = o0;
        *(float4*)&g_dist[off + 4] = o1;
    }
}

// ---------------- Weff = WlA + (A-B)@WlB ; beff = b2@WlB -------------------------
__global__ __launch_bounds__(128) void prep_weff_kernel(
    const float* __restrict__ W2, const float* __restrict__ b2,
    const float* __restrict__ Wl) {
    int c = threadIdx.x;
    if (blockIdx.x < 64) {
        int d = blockIdx.x;
        float acc = Wl[d * 128 + c];
        for (int e = 0; e < 128; e++)
            acc = fmaf(W2[d * 128 + e] - W2[(64 + d) * 128 + e],
                       Wl[(64 + e) * 128 + c], acc);
        g_Weff[d * 128 + c] = acc;
    } else {
        float acc = 0.f;
        for (int e = 0; e < 128; e++)
            acc = fmaf(b2[e], Wl[(64 + e) * 128 + c], acc);
        g_beff[c] = acc;
    }
}

// ---------------- EdgeConv2 v-branch: v2 = x1 @ W2[64:128] (8-pt staged) ---------
__global__ __launch_bounds__(256) void ec2_pre_kernel(const float* __restrict__ W2) {
    int c  = threadIdx.x & 127;
    int pg = threadIdx.x >> 7;   // 0 or 1
    float w[64];
#pragma unroll
    for (int d = 0; d < 64; d++) w[d] = W2[(64 + d) * 128 + c];

    __shared__ float xs[8][64];
    int p0 = blockIdx.x * 128;
    for (int r = 0; r < 16; r++) {
        int pb = p0 + r * 8;
#pragma unroll
        for (int s = 0; s < 2; s++) {
            int q = threadIdx.x + s * 256;
            xs[q >> 6][q & 63] = g_x1[(size_t)(pb + (q >> 6)) * 64 + (q & 63)];
        }
        __syncthreads();
#pragma unroll
        for (int pp = 0; pp < 4; pp++) {
            int p = pg + pp * 2;
            float y0 = 0.f, y1 = 0.f, y2 = 0.f, y3 = 0.f;
#pragma unroll
            for (int d = 0; d < 64; d += 16) {
                float4 q0 = *(const float4*)&xs[p][d];
                float4 q1 = *(const float4*)&xs[p][d + 4];
                float4 q2 = *(const float4*)&xs[p][d + 8];
                float4 q3 = *(const float4*)&xs[p][d + 12];
                y0 = fmaf(q0.x, w[d],    y0); y0 = fmaf(q0.y, w[d+1],  y0);
                y0 = fmaf(q0.z, w[d+2],  y0); y0 = fmaf(q0.w, w[d+3],  y0);
                y1 = fmaf(q1.x, w[d+4],  y1); y1 = fmaf(q1.y, w[d+5],  y1);
                y1 = fmaf(q1.z, w[d+6],  y1); y1 = fmaf(q1.w, w[d+7],  y1);
                y2 = fmaf(q2.x, w[d+8],  y2); y2 = fmaf(q2.y, w[d+9],  y2);
                y2 = fmaf(q2.z, w[d+10], y2); y2 = fmaf(q2.w, w[d+11], y2);
                y3 = fmaf(q3.x, w[d+12], y3); y3 = fmaf(q3.y, w[d+13], y3);
                y3 = fmaf(q3.z, w[d+14], y3); y3 = fmaf(q3.w, w[d+15], y3);
            }
            g_v2[(size_t)(pb + p) * 128 + c] = (y0 + y1) + (y2 + y3);
        }
        __syncthreads();
    }
}

// ---------------- EdgeConv2 neighbor max: m = max_k v2[nbr] (float4) -------------
__global__ __launch_bounds__(256) void ec2_combine_kernel() {
    int t = blockIdx.x * 256 + threadIdx.x;   // NPT*32 threads
    int i  = t >> 5;
    int c4 = (t & 31) << 2;
    int base = (i >> 10) << 10;
    float4 m = make_float4(-FLT_MAX, -FLT_MAX, -FLT_MAX, -FLT_MAX);
#pragma unroll
    for (int k = 0; k < KNN; k++) {
        int j = base + g_idx[i * KNN + k];
        float4 v = *(const float4*)&g_v2[(size_t)j * 128 + c4];
        m.x = fmaxf(m.x, v.x); m.y = fmaxf(m.y, v.y);
        m.z = fmaxf(m.z, v.z); m.w = fmaxf(m.w, v.w);
    }
    *(float4*)&g_m[(size_t)i * 128 + c4] = m;
}

// ---------------- fused final linear + running global max pool -------------------
__global__ __launch_bounds__(384) void finpool_kernel(const float* __restrict__ Wl) {
    int tid = threadIdx.x;
    int g = tid / 128;       // 0,1,2 (k-chunk group)
    int c = tid % 128;

    float w[64];
    if (g == 0) {
#pragma unroll
        for (int d = 0; d < 64; d++) w[d] = g_Weff[d * 128 + c];
    } else if (g == 1) {
#pragma unroll
        for (int d = 0; d < 64; d++) w[d] = Wl[(64 + d) * 128 + c];
    } else {
#pragma unroll
        for (int d = 0; d < 64; d++) w[d] = Wl[(128 + d) * 128 + c];
    }
    int off = (g == 0) ? 0 : ((g == 1) ? 64 : 128);

    __shared__ float xs[4][192];
    __shared__ float ps[3][4][128];
    float rm = -FLT_MAX;
    int p0 = blockIdx.x * 256;

    for (int r = 0; r < 64; r++) {
        int pb = p0 + r * 4;
#pragma unroll
        for (int s = 0; s < 2; s++) {
            int q = tid + s * 384;
            int p = q / 192, e = q % 192;
            xs[p][e] = (e < 64) ? g_x1[(size_t)(pb + p) * 64 + e]
                                : g_m[(size_t)(pb + p) * 128 + (e - 64)];
        }
        __syncthreads();
#pragma unroll
        for (int p = 0; p < 4; p++) {
            float y0 = 0.f, y1 = 0.f, y2 = 0.f, y3 = 0.f;
#pragma unroll
            for (int d = 0; d < 64; d += 16) {
                float4 q0 = *(const float4*)&xs[p][off + d];
                float4 q1 = *(const float4*)&xs[p][off + d + 4];
                float4 q2 = *(const float4*)&xs[p][off + d + 8];
                float4 q3 = *(const float4*)&xs[p][off + d + 12];
                y0 = fmaf(q0.x, w[d],    y0); y0 = fmaf(q0.y, w[d+1],  y0);
                y0 = fmaf(q0.z, w[d+2],  y0); y0 = fmaf(q0.w, w[d+3],  y0);
                y1 = fmaf(q1.x, w[d+4],  y1); y1 = fmaf(q1.y, w[d+5],  y1);
                y1 = fmaf(q1.z, w[d+6],  y1); y1 = fmaf(q1.w, w[d+7],  y1);
                y2 = fmaf(q2.x, w[d+8],  y2); y2 = fmaf(q2.y, w[d+9],  y2);
                y2 = fmaf(q2.z, w[d+10], y2); y2 = fmaf(q2.w, w[d+11], y2);
                y3 = fmaf(q3.x, w[d+12], y3); y3 = fmaf(q3.y, w[d+13], y3);
                y3 = fmaf(q3.z, w[d+14], y3); y3 = fmaf(q3.w, w[d+15], y3);
            }
            ps[g][p][c] = (y0 + y1) + (y2 + y3);
        }
        __syncthreads();
        if (g == 0) {
#pragma unroll
            for (int p = 0; p < 4; p++)
                rm = fmaxf(rm, ps[0][p][c] + ps[1][p][c] + ps[2][p][c]);
        }
    }
    if (g == 0) g_part[blockIdx.x * 128 + c] = rm;
}

// ---------------- final reduce over 4 segments per cloud -------------------------
__global__ void pool2_kernel(const float* __restrict__ bl, float* __restrict__ out) {
    int b = blockIdx.x;       // 32
    int c = threadIdx.x;      // 128
    float m = -FLT_MAX;
#pragma unroll
    for (int s = 0; s < 4; s++) m = fmaxf(m, g_part[(b * 4 + s) * 128 + c]);
    out[b * 128 + c] = m + g_beff[c] + bl[c];
}

// ---------------- launch --------------------------------------------------------
extern "C" void kernel_launch(void* const* d_in, const int* in_sizes, int n_in,
                              void* d_out, int out_size) {
    const float* pos = (const float*)d_in[0];
    const float* W1a = (const float*)d_in[1];
    const float* b1a = (const float*)d_in[2];
    const float* g1  = (const float*)d_in[3];
    const float* be1 = (const float*)d_in[4];
    const float* W1b = (const float*)d_in[5];
    const float* b1b = (const float*)d_in[6];
    const float* W2  = (const float*)d_in[7];
    const float* b2  = (const float*)d_in[8];
    const float* Wl  = (const float*)d_in[9];
    const float* bl  = (const float*)d_in[10];
    float* out = (float*)d_out;

    // knn on pos (fused dist + top-k)
    knn1_kernel<<<4096, 256>>>(pos);
    prep_weff_kernel<<<65, 128>>>(W2, b2, Wl);   // independent of point data

    // EdgeConv1
    ec1_pre_kernel<<<NPT * 64 / 256, 256>>>(pos, W1a, b1a);
    ec1_stats_kernel<<<STATS_BLOCKS, 256>>>();
    ec1_bn_kernel<<<1, 512>>>(g1, be1);
    ec1_apply_kernel<<<NPT / 4, 256>>>(W1b, b1b);

    // knn on x1
    n2_kernel<<<NPT / 256, 256>>>();
    gram_kernel<<<dim3(8, 8, BATCH), 256>>>();
    topk_kernel<<<NPT / 8, 256>>>();

    // EdgeConv2 (v-branch only; u-branch folded into Weff)
    ec2_pre_kernel<<<256, 256>>>(W2);
    ec2_combine_kernel<<<NPT * 32 / 256, 256>>>();

    // fused final linear + pool
    finpool_kernel<<<128, 384>>>(Wl);
    pool2_kernel<<<BATCH, 128>>>(bl, out);
}

// round 5
// speedup vs baseline: 1.5028x; 1.1252x over previous
#include <cuda_runtime.h>
#include <float.h>

#define BATCH 32
#define PTS   1024
#define NPT   (BATCH*PTS)     // 32768
#define KNN   20
#define EDGES (NPT*KNN)       // 655360
#define STATS_BLOCKS 1024

// ---------------- scratch (static device globals; no allocation) ----------------
__device__ float g_dist[(size_t)BATCH*PTS*PTS];   // 128 MB (knn2 only)
__device__ int   g_idx[NPT*KNN];
__device__ float g_u1[NPT*64];
__device__ float g_v1[NPT*64];
__device__ float g_x1[NPT*64];
__device__ float g_n2[NPT];
__device__ float g_part[STATS_BLOCKS*128];        // stats partials / pool partials
__device__ float g_scale[64];
__device__ float g_shift[64];
__device__ float g_v2[NPT*128];
__device__ float g_m[NPT*128];
__device__ float g_Weff[64*128];
__device__ float g_beff[128];

// ---------------- shared top-k machinery (lexicographic (val,idx)) ---------------
__device__ __forceinline__ bool kless(float v, int i, float w, int k) {
    return v < w || (v == w && i < k);
}

__device__ __forceinline__ void kinsert(float v, int j, float (&vals)[KNN], int (&ids)[KNN]) {
    if (kless(v, j, vals[KNN-1], ids[KNN-1])) {
        int pos = KNN - 1;
#pragma unroll
        for (int t = KNN - 2; t >= 0; t--)
            if (kless(v, j, vals[t], ids[t])) pos = t;
#pragma unroll
        for (int t = KNN - 1; t >= 0; t--) {
            if (t > pos)       { vals[t] = vals[t-1]; ids[t] = ids[t-1]; }
            else if (t == pos) { vals[t] = v;         ids[t] = j;        }
        }
    }
}

__device__ __forceinline__ void kmerge_write(float (&vals)[KNN], int (&ids)[KNN], int row) {
    int lane = threadIdx.x & 31;
    for (int r = 0; r < KNN; r++) {
        float cv = vals[0]; int ci = ids[0];
#pragma unroll
        for (int o = 16; o > 0; o >>= 1) {
            float ov = __shfl_xor_sync(0xffffffffu, cv, o);
            int   oi = __shfl_xor_sync(0xffffffffu, ci, o);
            if (kless(ov, oi, cv, ci)) { cv = ov; ci = oi; }
        }
        if (lane == 0) g_idx[row * KNN + r] = ci;
        if (ids[0] == ci && vals[0] == cv) {
#pragma unroll
            for (int t = 0; t < KNN - 1; t++) { vals[t] = vals[t+1]; ids[t] = ids[t+1]; }
            vals[KNN-1] = FLT_MAX; ids[KNN-1] = 0x7fffffff;
        }
    }
}

// ---------------- knn1 fused: dist-on-the-fly + top-20 + ec1_pre ----------------
__global__ __launch_bounds__(256) void knn1_kernel(
    const float* __restrict__ pos, const float* __restrict__ W1a,
    const float* __restrict__ b1a) {
    __shared__ float4 sp[PTS];   // 16 KB: {x,y,z,d2}
    __shared__ float sw[384];
    __shared__ float sb[64];
    int cloud  = blockIdx.x >> 7;
    int rowblk = blockIdx.x & 127;
    const float* pb = pos + (size_t)cloud * PTS * 3;
    for (int p = threadIdx.x; p < PTS; p += 256) {
        float x = pb[p*3], y = pb[p*3+1], z = pb[p*3+2];
        float d2 = __fadd_rn(__fadd_rn(__fmul_rn(x,x), __fmul_rn(y,y)), __fmul_rn(z,z));
        sp[p] = make_float4(x, y, z, d2);
    }
    for (int t = threadIdx.x; t < 384; t += 256) sw[t] = W1a[t];
    if (threadIdx.x < 64) sb[threadIdx.x] = b1a[threadIdx.x];
    __syncthreads();

    int warp = threadIdx.x >> 5, lane = threadIdx.x & 31;
    int il = rowblk * 8 + warp;
    float4 q = sp[il];

    float vals[KNN]; int ids[KNN];
#pragma unroll
    for (int t = 0; t < KNN; t++) { vals[t] = FLT_MAX; ids[t] = 0x7fffffff; }

    for (int t = 0; t < 32; t++) {
        int j = t * 32 + lane;
        float4 p = sp[j];
        float dot = __fadd_rn(__fadd_rn(__fmul_rn(q.x,p.x), __fmul_rn(q.y,p.y)), __fmul_rn(q.z,p.z));
        float v = __fsub_rn(__fadd_rn(q.w, p.w), __fmul_rn(2.0f, dot));
        kinsert(v, j, vals, ids);
    }
    kmerge_write(vals, ids, cloud * PTS + il);

    // fused ec1_pre: u = x@(A-B)+b1a, v = x@B for this block's 8 points
    int c = threadIdx.x & 63;
#pragma unroll
    for (int rep = 0; rep < 2; rep++) {
        int pl  = (threadIdx.x >> 6) + rep * 4;
        int il2 = rowblk * 8 + pl;
        float4 P = sp[il2];
        float a  = P.x * sw[c]       + P.y * sw[64 + c]  + P.z * sw[128 + c];
        float bb = P.x * sw[192 + c] + P.y * sw[256 + c] + P.z * sw[320 + c];
        int gp = ((cloud << 10) + il2) * 64 + c;
        g_u1[gp] = a - bb + sb[c];
        g_v1[gp] = bb;
    }
}

// ---------------- knn2 top-k (reads g_dist, float4 per lane) ---------------------
__global__ __launch_bounds__(256) void topk_kernel() {
    int warp = (blockIdx.x * blockDim.x + threadIdx.x) >> 5;
    int lane = threadIdx.x & 31;
    if (warp >= NPT) return;
    const float4* row = (const float4*)(g_dist + ((size_t)warp << 10));

    float vals[KNN]; int ids[KNN];
#pragma unroll
    for (int t = 0; t < KNN; t++) { vals[t] = FLT_MAX; ids[t] = 0x7fffffff; }
#pragma unroll
    for (int t = 0; t < 8; t++) {
        int e = t * 32 + lane;
        float4 v = row[e];
        int j = e << 2;
        kinsert(v.x, j,     vals, ids);
        kinsert(v.y, j + 1, vals, ids);
        kinsert(v.z, j + 2, vals, ids);
        kinsert(v.w, j + 3, vals, ids);
    }
    kmerge_write(vals, ids, warp);
}

// ---------------- BN stats: per-point algebraic fold -----------------------------
__global__ __launch_bounds__(256) void ec1_stats_kernel() {
    int c  = threadIdx.x & 63;
    int sl = threadIdx.x >> 6;   // 0..3
    int p0 = blockIdx.x * 32;    // 1024 blocks x 32 points
    float s = 0.f, s2 = 0.f;
    for (int pp = sl; pp < 32; pp += 4) {
        int p = p0 + pp;
        int base = (p >> 10) << 10;
        float u = g_u1[p * 64 + c];
        int id[KNN];
#pragma unroll
        for (int k = 0; k < KNN; k++) id[k] = g_idx[p * KNN + k];
        float S = 0.f, T = 0.f;
#pragma unroll
        for (int k = 0; k < KNN; k++) {
            float v = g_v1[(base + id[k]) * 64 + c];
            S += v;
            T = fmaf(v, v, T);
        }
        s  += fmaf(20.0f, u, S);
        s2 += fmaf(u, fmaf(20.0f, u, 2.0f * S), T);
    }
    __shared__ float sh[2][4][64];
    sh[0][sl][c] = s; sh[1][sl][c] = s2;
    __syncthreads();
    if (sl == 0) {
        float ts = sh[0][0][c] + sh[0][1][c] + sh[0][2][c] + sh[0][3][c];
        float t2 = sh[1][0][c] + sh[1][1][c] + sh[1][2][c] + sh[1][3][c];
        g_part[blockIdx.x * 128 + c]      = ts;
        g_part[blockIdx.x * 128 + 64 + c] = t2;
    }
}

// ---------------- BN finalize ------------------------------------------------------
__global__ __launch_bounds__(512) void ec1_bn_kernel(
    const float* __restrict__ g1, const float* __restrict__ be1) {
    int c = threadIdx.x & 63;
    int g = threadIdx.x >> 6;    // 0..7
    float s = 0.f, s2 = 0.f;
    for (int b = g; b < STATS_BLOCKS; b += 8) {
        s  += g_part[b * 128 + c];
        s2 += g_part[b * 128 + 64 + c];
    }
    __shared__ float sh[8][64], sh2[8][64];
    sh[g][c] = s; sh2[g][c] = s2;
    __syncthreads();
    if (g == 0) {
        float ts = 0.f, t2 = 0.f;
#pragma unroll
        for (int r = 0; r < 8; r++) { ts += sh[r][c]; t2 += sh2[r][c]; }
        float n   = (float)EDGES;
        float mu  = ts / n;
        float var = t2 / n - mu * mu;
        float sc  = g1[c] * rsqrtf(var + 1e-5f);
        g_scale[c] = sc;
        g_shift[c] = be1[c] - mu * sc;
    }
}

// ---------------- EdgeConv1 apply: stage 20 relu'd edges, GEMV, max; + n2 --------
__global__ __launch_bounds__(256) void ec1_apply_kernel(
    const float* __restrict__ W1b, const float* __restrict__ b1b) {
    int pt = threadIdx.x >> 6;     // 4 points per block
    int c  = threadIdx.x & 63;
    int i  = blockIdx.x * 4 + pt;

    float w[64];
#pragma unroll
    for (int d = 0; d < 64; d++) w[d] = W1b[d * 64 + c];

    __shared__ float hb[4][KNN][64];
    float sc  = g_scale[c], shv = g_shift[c];
    float a   = fmaf(g_u1[i * 64 + c], sc, shv);
    int  base = (i >> 10) << 10;

    int id[KNN];
#pragma unroll
    for (int k = 0; k < KNN; k++) id[k] = g_idx[i * KNN + k];
#pragma unroll
    for (int k = 0; k < KNN; k++)
        hb[pt][k][c] = fmaxf(fmaf(g_v1[(base + id[k]) * 64 + c], sc, a), 0.0f);
    __syncthreads();

    float bb  = b1b[c];
    float acc = -FLT_MAX;
#pragma unroll
    for (int k = 0; k < KNN; k++) {
        float y0 = bb, y1 = 0.f, y2 = 0.f, y3 = 0.f;
#pragma unroll
        for (int d = 0; d < 64; d += 16) {
            float4 p0 = *(const float4*)&hb[pt][k][d];
            float4 p1 = *(const float4*)&hb[pt][k][d + 4];
            float4 p2 = *(const float4*)&hb[pt][k][d + 8];
            float4 p3 = *(const float4*)&hb[pt][k][d + 12];
            y0 = fmaf(p0.x, w[d],    y0); y0 = fmaf(p0.y, w[d+1],  y0);
            y0 = fmaf(p0.z, w[d+2],  y0); y0 = fmaf(p0.w, w[d+3],  y0);
            y1 = fmaf(p1.x, w[d+4],  y1); y1 = fmaf(p1.y, w[d+5],  y1);
            y1 = fmaf(p1.z, w[d+6],  y1); y1 = fmaf(p1.w, w[d+7],  y1);
            y2 = fmaf(p2.x, w[d+8],  y2); y2 = fmaf(p2.y, w[d+9],  y2);
            y2 = fmaf(p2.z, w[d+10], y2); y2 = fmaf(p2.w, w[d+11], y2);
            y3 = fmaf(p3.x, w[d+12], y3); y3 = fmaf(p3.y, w[d+13], y3);
            y3 = fmaf(p3.z, w[d+14], y3); y3 = fmaf(p3.w, w[d+15], y3);
        }
        acc = fmaxf(acc, (y0 + y1) + (y2 + y3));
    }
    g_x1[i * 64 + c] = acc;

    // fused n2: squared norm per point
    __shared__ float nsq[4][64];
    __shared__ float npart[4][8];
    nsq[pt][c] = acc * acc;
    __syncthreads();
    if (c < 8) {
        float s = 0.f;
#pragma unroll
        for (int m = 0; m < 8; m++) s += nsq[pt][c * 8 + m];
        npart[pt][c] = s;
    }
    __syncthreads();
    if (c == 0) {
        float s = 0.f;
#pragma unroll
        for (int m = 0; m < 8; m++) s += npart[pt][m];
        g_n2[i] = s;
    }
}

// ---------------- knn2: Gram GEMM, 128x128 tile / 8x8 microtile ------------------
__global__ __launch_bounds__(256) void gram_kernel() {
    int b  = blockIdx.z;
    int i0 = blockIdx.y << 7;
    int j0 = blockIdx.x << 7;
    const float* xb = g_x1 + ((size_t)b << 10) * 64;

    __shared__ float As[16][132];
    __shared__ float Bs[16][132];

    int tid = threadIdx.x;
    int tx = tid & 15, ty = tid >> 4;
    int lr = tid >> 2, lc4 = tid & 3;

    float acc[8][8];
#pragma unroll
    for (int r = 0; r < 8; r++)
#pragma unroll
        for (int s = 0; s < 8; s++) acc[r][s] = 0.f;

    for (int k0 = 0; k0 < 64; k0 += 16) {
#pragma unroll
        for (int half = 0; half < 2; half++) {
            int r = lr + half * 64;
            float4 av = *(const float4*)&xb[(i0 + r) * 64 + k0 + lc4 * 4];
            float4 bv = *(const float4*)&xb[(j0 + r) * 64 + k0 + lc4 * 4];
            As[lc4*4+0][r] = av.x; As[lc4*4+1][r] = av.y;
            As[lc4*4+2][r] = av.z; As[lc4*4+3][r] = av.w;
            Bs[lc4*4+0][r] = bv.x; Bs[lc4*4+1][r] = bv.y;
            Bs[lc4*4+2][r] = bv.z; Bs[lc4*4+3][r] = bv.w;
        }
        __syncthreads();
#pragma unroll
        for (int k = 0; k < 16; k++) {
            float4 a0 = *(const float4*)&As[k][ty << 3];
            float4 a1 = *(const float4*)&As[k][(ty << 3) + 4];
            float4 b0 = *(const float4*)&Bs[k][tx << 3];
            float4 b1 = *(const float4*)&Bs[k][(tx << 3) + 4];
            float ar[8] = {a0.x, a0.y, a0.z, a0.w, a1.x, a1.y, a1.z, a1.w};
            float br[8] = {b0.x, b0.y, b0.z, b0.w, b1.x, b1.y, b1.z, b1.w};
#pragma unroll
            for (int r = 0; r < 8; r++)
#pragma unroll
                for (int s = 0; s < 8; s++) acc[r][s] = fmaf(ar[r], br[s], acc[r][s]);
        }
        __syncthreads();
    }

    float nj[8];
#pragma unroll
    for (int s = 0; s < 8; s++) nj[s] = g_n2[(b << 10) + j0 + (tx << 3) + s];
#pragma unroll
    for (int r = 0; r < 8; r++) {
        int i = i0 + (ty << 3) + r;
        float ni = g_n2[(b << 10) + i];
        float4 o0, o1;
        o0.x = __fsub_rn(__fadd_rn(ni, nj[0]), __fmul_rn(2.0f, acc[r][0]));
        o0.y = __fsub_rn(__fadd_rn(ni, nj[1]), __fmul_rn(2.0f, acc[r][1]));
        o0.z = __fsub_rn(__fadd_rn(ni, nj[2]), __fmul_rn(2.0f, acc[r][2]));
        o0.w = __fsub_rn(__fadd_rn(ni, nj[3]), __fmul_rn(2.0f, acc[r][3]));
        o1.x = __fsub_rn(__fadd_rn(ni, nj[4]), __fmul_rn(2.0f, acc[r][4]));
        o1.y = __fsub_rn(__fadd_rn(ni, nj[5]), __fmul_rn(2.0f, acc[r][5]));
        o1.z = __fsub_rn(__fadd_rn(ni, nj[6]), __fmul_rn(2.0f, acc[r][6]));
        o1.w = __fsub_rn(__fadd_rn(ni, nj[7]), __fmul_rn(2.0f, acc[r][7]));
        size_t off = ((size_t)b << 20) + ((size_t)i << 10) + j0 + (tx << 3);
        *(float4*)&g_dist[off]     = o0;
        *(float4*)&g_dist[off + 4] = o1;
    }
}

// ---------------- Weff = WlA + (A-B)@WlB ; beff = b2@WlB -------------------------
__global__ __launch_bounds__(128) void prep_weff_kernel(
    const float* __restrict__ W2, const float* __restrict__ b2,
    const float* __restrict__ Wl) {
    int c = threadIdx.x;
    if (blockIdx.x < 64) {
        int d = blockIdx.x;
        float a0 = 0.f, a1 = 0.f, a2 = 0.f, a3 = 0.f;
        for (int e = 0; e < 128; e += 4) {
            a0 = fmaf(W2[d*128+e]   - W2[(64+d)*128+e],   Wl[(64+e)*128+c],   a0);
            a1 = fmaf(W2[d*128+e+1] - W2[(64+d)*128+e+1], Wl[(64+e+1)*128+c], a1);
            a2 = fmaf(W2[d*128+e+2] - W2[(64+d)*128+e+2], Wl[(64+e+2)*128+c], a2);
            a3 = fmaf(W2[d*128+e+3] - W2[(64+d)*128+e+3], Wl[(64+e+3)*128+c], a3);
        }
        g_Weff[d * 128 + c] = Wl[d * 128 + c] + ((a0 + a1) + (a2 + a3));
    } else {
        float a0 = 0.f, a1 = 0.f;
        for (int e = 0; e < 128; e += 2) {
            a0 = fmaf(b2[e],     Wl[(64+e)*128+c],   a0);
            a1 = fmaf(b2[e+1],   Wl[(64+e+1)*128+c], a1);
        }
        g_beff[c] = a0 + a1;
    }
}

// ---------------- EdgeConv2 v-branch: v2 = x1 @ W2[64:128] (8-pt staged) ---------
__global__ __launch_bounds__(256) void ec2_pre_kernel(const float* __restrict__ W2) {
    int c  = threadIdx.x & 127;
    int pg = threadIdx.x >> 7;   // 0 or 1
    float w[64];
#pragma unroll
    for (int d = 0; d < 64; d++) w[d] = W2[(64 + d) * 128 + c];

    __shared__ float xs[8][64];
    int p0 = blockIdx.x * 128;
    for (int r = 0; r < 16; r++) {
        int pb = p0 + r * 8;
#pragma unroll
        for (int s = 0; s < 2; s++) {
            int q = threadIdx.x + s * 256;
            xs[q >> 6][q & 63] = g_x1[(size_t)(pb + (q >> 6)) * 64 + (q & 63)];
        }
        __syncthreads();
#pragma unroll
        for (int pp = 0; pp < 4; pp++) {
            int p = pg + pp * 2;
            float y0 = 0.f, y1 = 0.f, y2 = 0.f, y3 = 0.f;
#pragma unroll
            for (int d = 0; d < 64; d += 16) {
                float4 q0 = *(const float4*)&xs[p][d];
                float4 q1 = *(const float4*)&xs[p][d + 4];
                float4 q2 = *(const float4*)&xs[p][d + 8];
                float4 q3 = *(const float4*)&xs[p][d + 12];
                y0 = fmaf(q0.x, w[d],    y0); y0 = fmaf(q0.y, w[d+1],  y0);
                y0 = fmaf(q0.z, w[d+2],  y0); y0 = fmaf(q0.w, w[d+3],  y0);
                y1 = fmaf(q1.x, w[d+4],  y1); y1 = fmaf(q1.y, w[d+5],  y1);
                y1 = fmaf(q1.z, w[d+6],  y1); y1 = fmaf(q1.w, w[d+7],  y1);
                y2 = fmaf(q2.x, w[d+8],  y2); y2 = fmaf(q2.y, w[d+9],  y2);
                y2 = fmaf(q2.z, w[d+10], y2); y2 = fmaf(q2.w, w[d+11], y2);
                y3 = fmaf(q3.x, w[d+12], y3); y3 = fmaf(q3.y, w[d+13], y3);
                y3 = fmaf(q3.z, w[d+14], y3); y3 = fmaf(q3.w, w[d+15], y3);
            }
            g_v2[(size_t)(pb + p) * 128 + c] = (y0 + y1) + (y2 + y3);
        }
        __syncthreads();
    }
}

// ---------------- EdgeConv2 neighbor max: m = max_k v2[nbr] (float4) -------------
__global__ __launch_bounds__(256) void ec2_combine_kernel() {
    int t = blockIdx.x * 256 + threadIdx.x;   // NPT*32 threads
    int i  = t >> 5;
    int c4 = (t & 31) << 2;
    int base = (i >> 10) << 10;
    int id[KNN];
#pragma unroll
    for (int k = 0; k < KNN; k++) id[k] = g_idx[i * KNN + k];
    float4 m = make_float4(-FLT_MAX, -FLT_MAX, -FLT_MAX, -FLT_MAX);
#pragma unroll
    for (int k = 0; k < KNN; k++) {
        float4 v = *(const float4*)&g_v2[(size_t)(base + id[k]) * 128 + c4];
        m.x = fmaxf(m.x, v.x); m.y = fmaxf(m.y, v.y);
        m.z = fmaxf(m.z, v.z); m.w = fmaxf(m.w, v.w);
    }
    *(float4*)&g_m[(size_t)i * 128 + c4] = m;
}

// ---------------- fused final linear + running global max pool -------------------
__global__ __launch_bounds__(384) void finpool_kernel(const float* __restrict__ Wl) {
    int tid = threadIdx.x;
    int g = tid / 128;       // 0,1,2 (k-chunk group)
    int c = tid % 128;

    float w[64];
    if (g == 0) {
#pragma unroll
        for (int d = 0; d < 64; d++) w[d] = g_Weff[d * 128 + c];
    } else if (g == 1) {
#pragma unroll
        for (int d = 0; d < 64; d++) w[d] = Wl[(64 + d) * 128 + c];
    } else {
#pragma unroll
        for (int d = 0; d < 64; d++) w[d] = Wl[(128 + d) * 128 + c];
    }
    int off = (g == 0) ? 0 : ((g == 1) ? 64 : 128);

    __shared__ float xs[4][192];
    __shared__ float ps[3][4][128];
    float rm = -FLT_MAX;
    int p0 = blockIdx.x * 256;

    for (int r = 0; r < 64; r++) {
        int pb = p0 + r * 4;
#pragma unroll
        for (int s = 0; s < 2; s++) {
            int q = tid + s * 384;
            int p = q / 192, e = q % 192;
            xs[p][e] = (e < 64) ? g_x1[(size_t)(pb + p) * 64 + e]
                                : g_m[(size_t)(pb + p) * 128 + (e - 64)];
        }
        __syncthreads();
#pragma unroll
        for (int p = 0; p < 4; p++) {
            float y0 = 0.f, y1 = 0.f, y2 = 0.f, y3 = 0.f;
#pragma unroll
            for (int d = 0; d < 64; d += 16) {
                float4 q0 = *(const float4*)&xs[p][off + d];
                float4 q1 = *(const float4*)&xs[p][off + d + 4];
                float4 q2 = *(const float4*)&xs[p][off + d + 8];
                float4 q3 = *(const float4*)&xs[p][off + d + 12];
                y0 = fmaf(q0.x, w[d],    y0); y0 = fmaf(q0.y, w[d+1],  y0);
                y0 = fmaf(q0.z, w[d+2],  y0); y0 = fmaf(q0.w, w[d+3],  y0);
                y1 = fmaf(q1.x, w[d+4],  y1); y1 = fmaf(q1.y, w[d+5],  y1);
                y1 = fmaf(q1.z, w[d+6],  y1); y1 = fmaf(q1.w, w[d+7],  y1);
                y2 = fmaf(q2.x, w[d+8],  y2); y2 = fmaf(q2.y, w[d+9],  y2);
                y2 = fmaf(q2.z, w[d+10], y2); y2 = fmaf(q2.w, w[d+11], y2);
                y3 = fmaf(q3.x, w[d+12], y3); y3 = fmaf(q3.y, w[d+13], y3);
                y3 = fmaf(q3.z, w[d+14], y3); y3 = fmaf(q3.w, w[d+15], y3);
            }
            ps[g][p][c] = (y0 + y1) + (y2 + y3);
        }
        __syncthreads();
        if (g == 0) {
#pragma unroll
            for (int p = 0; p < 4; p++)
                rm = fmaxf(rm, ps[0][p][c] + ps[1][p][c] + ps[2][p][c]);
        }
    }
    if (g == 0) g_part[blockIdx.x * 128 + c] = rm;
}

// ---------------- final reduce over 4 segments per cloud -------------------------
__global__ void pool2_kernel(const float* __restrict__ bl, float* __restrict__ out) {
    int b = blockIdx.x;       // 32
    int c = threadIdx.x;      // 128
    float m = -FLT_MAX;
#pragma unroll
    for (int s = 0; s < 4; s++) m = fmaxf(m, g_part[(b * 4 + s) * 128 + c]);
    out[b * 128 + c] = m + g_beff[c] + bl[c];
}

// ---------------- launch --------------------------------------------------------
extern "C" void kernel_launch(void* const* d_in, const int* in_sizes, int n_in,
                              void* d_out, int out_size) {
    const float* pos = (const float*)d_in[0];
    const float* W1a = (const float*)d_in[1];
    const float* b1a = (const float*)d_in[2];
    const float* g1  = (const float*)d_in[3];
    const float* be1 = (const float*)d_in[4];
    const float* W1b = (const float*)d_in[5];
    const float* b1b = (const float*)d_in[6];
    const float* W2  = (const float*)d_in[7];
    const float* b2  = (const float*)d_in[8];
    const float* Wl  = (const float*)d_in[9];
    const float* bl  = (const float*)d_in[10];
    float* out = (float*)d_out;

    // knn on pos (fused dist + top-k + ec1_pre)
    knn1_kernel<<<4096, 256>>>(pos, W1a, b1a);
    prep_weff_kernel<<<65, 128>>>(W2, b2, Wl);   // independent of point data

    // EdgeConv1
    ec1_stats_kernel<<<STATS_BLOCKS, 256>>>();
    ec1_bn_kernel<<<1, 512>>>(g1, be1);
    ec1_apply_kernel<<<NPT / 4, 256>>>(W1b, b1b);   // + fused n2

    // knn on x1
    gram_kernel<<<dim3(8, 8, BATCH), 256>>>();
    topk_kernel<<<NPT / 8, 256>>>();

    // EdgeConv2 (v-branch only; u-branch folded into Weff)
    ec2_pre_kernel<<<256, 256>>>(W2);
    ec2_combine_kernel<<<NPT * 32 / 256, 256>>>();

    // fused final linear + pool
    finpool_kernel<<<128, 384>>>(Wl);
    pool2_kernel<<<BATCH, 128>>>(bl, out);
}

// round 6
// speedup vs baseline: 1.6780x; 1.1166x over previous
#include <cuda_runtime.h>
#include <float.h>

#define BATCH 32
#define PTS   1024
#define NPT   (BATCH*PTS)     // 32768
#define KNN   20
#define EDGES (NPT*KNN)       // 655360
#define STATS_BLOCKS 1024
#define KEY_MAX 0xFFFFFFFFFFFFFFFFull

// ---------------- scratch (static device globals; no allocation) ----------------
__device__ float g_dist[(size_t)BATCH*PTS*PTS];   // 128 MB (knn2 only)
__device__ int   g_idx[NPT*KNN];
__device__ float g_u1[NPT*64];
__device__ float g_v1[NPT*64];
__device__ float g_x1[NPT*64];
__device__ float g_n2[NPT];
__device__ float g_part[STATS_BLOCKS*128];        // stats partials / pool partials
__device__ float g_scale[64];
__device__ float g_shift[64];
__device__ float g_v2[NPT*128];
__device__ float g_m[NPT*128];
__device__ float g_Weff[64*128];
__device__ float g_beff[128];

// ---------------- u64-key top-k: key = monotonic(dist) << 32 | j -----------------
__device__ __forceinline__ unsigned long long fkey(float v, int j) {
    unsigned int b = __float_as_uint(v);
    b = (b & 0x80000000u) ? ~b : (b | 0x80000000u);   // total order on floats
    return ((unsigned long long)b << 32) | (unsigned int)j;
}

__device__ __forceinline__ void kinsert64(unsigned long long k,
                                          unsigned long long (&keys)[KNN]) {
    if (k < keys[KNN-1]) {
        int pos = KNN - 1;
#pragma unroll
        for (int t = KNN - 2; t >= 0; t--)
            if (k < keys[t]) pos = t;
#pragma unroll
        for (int t = KNN - 1; t >= 0; t--) {
            if (t > pos)       keys[t] = keys[t-1];
            else if (t == pos) keys[t] = k;
        }
    }
}

__device__ __forceinline__ void kmerge_write64(unsigned long long (&keys)[KNN], int row) {
    int lane = threadIdx.x & 31;
    for (int r = 0; r < KNN; r++) {
        unsigned long long ck = keys[0];
#pragma unroll
        for (int o = 16; o > 0; o >>= 1) {
            unsigned long long ok = __shfl_xor_sync(0xffffffffu, ck, o);
            if (ok < ck) ck = ok;
        }
        if (lane == 0) g_idx[row * KNN + r] = (int)(unsigned int)(ck & 0xFFFFFFFFull);
        if (keys[0] == ck) {
#pragma unroll
            for (int t = 0; t < KNN - 1; t++) keys[t] = keys[t+1];
            keys[KNN-1] = KEY_MAX;
        }
    }
}

// ---------------- knn1 fused: dist-on-the-fly + top-20 + ec1_pre ----------------
__global__ __launch_bounds__(512) void knn1_kernel(
    const float* __restrict__ pos, const float* __restrict__ W1a,
    const float* __restrict__ b1a) {
    __shared__ float4 sp[PTS];   // 16 KB: {x,y,z,d2}
    __shared__ float sw[384];
    __shared__ float sb[64];
    int cloud  = blockIdx.x >> 6;      // 64 blocks per cloud, 16 rows per block
    int rowblk = blockIdx.x & 63;
    const float* pb = pos + (size_t)cloud * PTS * 3;
    for (int p = threadIdx.x; p < PTS; p += 512) {
        float x = pb[p*3], y = pb[p*3+1], z = pb[p*3+2];
        float d2 = __fadd_rn(__fadd_rn(__fmul_rn(x,x), __fmul_rn(y,y)), __fmul_rn(z,z));
        sp[p] = make_float4(x, y, z, d2);
    }
    for (int t = threadIdx.x; t < 384; t += 512) sw[t] = W1a[t];
    if (threadIdx.x < 64) sb[threadIdx.x] = b1a[threadIdx.x];
    __syncthreads();

    int warp = threadIdx.x >> 5, lane = threadIdx.x & 31;
    int il = rowblk * 16 + warp;
    float4 q = sp[il];

    unsigned long long keys[KNN];
#pragma unroll
    for (int t = 0; t < KNN; t++) keys[t] = KEY_MAX;

    for (int t = 0; t < 32; t++) {
        int j = t * 32 + lane;
        float4 p = sp[j];
        float dot = __fadd_rn(__fadd_rn(__fmul_rn(q.x,p.x), __fmul_rn(q.y,p.y)), __fmul_rn(q.z,p.z));
        float v = __fsub_rn(__fadd_rn(q.w, p.w), __fmul_rn(2.0f, dot));
        kinsert64(fkey(v, j), keys);
    }
    kmerge_write64(keys, cloud * PTS + il);

    // fused ec1_pre: u = x@(A-B)+b1a, v = x@B for this block's 16 points
    int c = threadIdx.x & 63;
#pragma unroll
    for (int rep = 0; rep < 2; rep++) {
        int pl  = (threadIdx.x >> 6) + rep * 8;
        int il2 = rowblk * 16 + pl;
        float4 P = sp[il2];
        float a  = P.x * sw[c]       + P.y * sw[64 + c]  + P.z * sw[128 + c];
        float bb = P.x * sw[192 + c] + P.y * sw[256 + c] + P.z * sw[320 + c];
        int gp = ((cloud << 10) + il2) * 64 + c;
        g_u1[gp] = a - bb + sb[c];
        g_v1[gp] = bb;
    }
}

// ---------------- knn2 top-k (reads g_dist, float4 per lane) ---------------------
__global__ __launch_bounds__(256) void topk_kernel() {
    int warp = (blockIdx.x * blockDim.x + threadIdx.x) >> 5;
    int lane = threadIdx.x & 31;
    if (warp >= NPT) return;
    const float4* row = (const float4*)(g_dist + ((size_t)warp << 10));

    unsigned long long keys[KNN];
#pragma unroll
    for (int t = 0; t < KNN; t++) keys[t] = KEY_MAX;
#pragma unroll
    for (int t = 0; t < 8; t++) {
        int e = t * 32 + lane;
        float4 v = row[e];
        int j = e << 2;
        kinsert64(fkey(v.x, j),     keys);
        kinsert64(fkey(v.y, j + 1), keys);
        kinsert64(fkey(v.z, j + 2), keys);
        kinsert64(fkey(v.w, j + 3), keys);
    }
    kmerge_write64(keys, warp);
}

// ---------------- BN stats: per-point algebraic fold -----------------------------
__global__ __launch_bounds__(256) void ec1_stats_kernel() {
    int c  = threadIdx.x & 63;
    int sl = threadIdx.x >> 6;   // 0..3
    int p0 = blockIdx.x * 32;    // 1024 blocks x 32 points
    float s = 0.f, s2 = 0.f;
    for (int pp = sl; pp < 32; pp += 4) {
        int p = p0 + pp;
        int base = (p >> 10) << 10;
        float u = g_u1[p * 64 + c];
        int id[KNN];
#pragma unroll
        for (int k = 0; k < KNN; k++) id[k] = g_idx[p * KNN + k];
        float S = 0.f, T = 0.f;
#pragma unroll
        for (int k = 0; k < KNN; k++) {
            float v = g_v1[(base + id[k]) * 64 + c];
            S += v;
            T = fmaf(v, v, T);
        }
        s  += fmaf(20.0f, u, S);
        s2 += fmaf(u, fmaf(20.0f, u, 2.0f * S), T);
    }
    __shared__ float sh[2][4][64];
    sh[0][sl][c] = s; sh[1][sl][c] = s2;
    __syncthreads();
    if (sl == 0) {
        float ts = sh[0][0][c] + sh[0][1][c] + sh[0][2][c] + sh[0][3][c];
        float t2 = sh[1][0][c] + sh[1][1][c] + sh[1][2][c] + sh[1][3][c];
        g_part[blockIdx.x * 128 + c]      = ts;
        g_part[blockIdx.x * 128 + 64 + c] = t2;
    }
}

// ---------------- BN finalize (16-way partials) -----------------------------------
__global__ __launch_bounds__(1024) void ec1_bn_kernel(
    const float* __restrict__ g1, const float* __restrict__ be1) {
    int c = threadIdx.x & 63;
    int g = threadIdx.x >> 6;    // 0..15
    float s = 0.f, s2 = 0.f;
    for (int b = g; b < STATS_BLOCKS; b += 16) {
        s  += g_part[b * 128 + c];
        s2 += g_part[b * 128 + 64 + c];
    }
    __shared__ float sh[16][64], sh2[16][64];
    sh[g][c] = s; sh2[g][c] = s2;
    __syncthreads();
    if (g == 0) {
        float ts = 0.f, t2 = 0.f;
#pragma unroll
        for (int r = 0; r < 16; r++) { ts += sh[r][c]; t2 += sh2[r][c]; }
        float n   = (float)EDGES;
        float mu  = ts / n;
        float var = t2 / n - mu * mu;
        float sc  = g1[c] * rsqrtf(var + 1e-5f);
        g_scale[c] = sc;
        g_shift[c] = be1[c] - mu * sc;
    }
}

// ---------------- EdgeConv1 apply: stage 20 relu'd edges, GEMV, max; + n2 --------
__global__ __launch_bounds__(256) void ec1_apply_kernel(
    const float* __restrict__ W1b, const float* __restrict__ b1b) {
    int pt = threadIdx.x >> 6;     // 4 points per block
    int c  = threadIdx.x & 63;
    int i  = blockIdx.x * 4 + pt;

    float w[64];
#pragma unroll
    for (int d = 0; d < 64; d++) w[d] = W1b[d * 64 + c];

    __shared__ float hb[4][KNN][64];
    float sc  = g_scale[c], shv = g_shift[c];
    float a   = fmaf(g_u1[i * 64 + c], sc, shv);
    int  base = (i >> 10) << 10;

    int id[KNN];
#pragma unroll
    for (int k = 0; k < KNN; k++) id[k] = g_idx[i * KNN + k];
#pragma unroll
    for (int k = 0; k < KNN; k++)
        hb[pt][k][c] = fmaxf(fmaf(g_v1[(base + id[k]) * 64 + c], sc, a), 0.0f);
    __syncthreads();

    float bb  = b1b[c];
    float acc = -FLT_MAX;
#pragma unroll
    for (int k = 0; k < KNN; k++) {
        float y0 = bb, y1 = 0.f, y2 = 0.f, y3 = 0.f;
#pragma unroll
        for (int d = 0; d < 64; d += 16) {
            float4 p0 = *(const float4*)&hb[pt][k][d];
            float4 p1 = *(const float4*)&hb[pt][k][d + 4];
            float4 p2 = *(const float4*)&hb[pt][k][d + 8];
            float4 p3 = *(const float4*)&hb[pt][k][d + 12];
            y0 = fmaf(p0.x, w[d],    y0); y0 = fmaf(p0.y, w[d+1],  y0);
            y0 = fmaf(p0.z, w[d+2],  y0); y0 = fmaf(p0.w, w[d+3],  y0);
            y1 = fmaf(p1.x, w[d+4],  y1); y1 = fmaf(p1.y, w[d+5],  y1);
            y1 = fmaf(p1.z, w[d+6],  y1); y1 = fmaf(p1.w, w[d+7],  y1);
            y2 = fmaf(p2.x, w[d+8],  y2); y2 = fmaf(p2.y, w[d+9],  y2);
            y2 = fmaf(p2.z, w[d+10], y2); y2 = fmaf(p2.w, w[d+11], y2);
            y3 = fmaf(p3.x, w[d+12], y3); y3 = fmaf(p3.y, w[d+13], y3);
            y3 = fmaf(p3.z, w[d+14], y3); y3 = fmaf(p3.w, w[d+15], y3);
        }
        acc = fmaxf(acc, (y0 + y1) + (y2 + y3));
    }
    g_x1[i * 64 + c] = acc;

    // fused n2: squared norm per point
    __shared__ float nsq[4][64];
    __shared__ float npart[4][8];
    nsq[pt][c] = acc * acc;
    __syncthreads();
    if (c < 8) {
        float s = 0.f;
#pragma unroll
        for (int m = 0; m < 8; m++) s += nsq[pt][c * 8 + m];
        npart[pt][c] = s;
    }
    __syncthreads();
    if (c == 0) {
        float s = 0.f;
#pragma unroll
        for (int m = 0; m < 8; m++) s += npart[pt][m];
        g_n2[i] = s;
    }
}

// ---------------- knn2: Gram GEMM, 128x128 tile / 8x8 microtile ------------------
__global__ __launch_bounds__(256) void gram_kernel() {
    int b  = blockIdx.z;
    int i0 = blockIdx.y << 7;
    int j0 = blockIdx.x << 7;
    const float* xb = g_x1 + ((size_t)b << 10) * 64;

    __shared__ float As[16][132];
    __shared__ float Bs[16][132];

    int tid = threadIdx.x;
    int tx = tid & 15, ty = tid >> 4;
    int lr = tid >> 2, lc4 = tid & 3;

    float acc[8][8];
#pragma unroll
    for (int r = 0; r < 8; r++)
#pragma unroll
        for (int s = 0; s < 8; s++) acc[r][s] = 0.f;

    for (int k0 = 0; k0 < 64; k0 += 16) {
#pragma unroll
        for (int half = 0; half < 2; half++) {
            int r = lr + half * 64;
            float4 av = *(const float4*)&xb[(i0 + r) * 64 + k0 + lc4 * 4];
            float4 bv = *(const float4*)&xb[(j0 + r) * 64 + k0 + lc4 * 4];
            As[lc4*4+0][r] = av.x; As[lc4*4+1][r] = av.y;
            As[lc4*4+2][r] = av.z; As[lc4*4+3][r] = av.w;
            Bs[lc4*4+0][r] = bv.x; Bs[lc4*4+1][r] = bv.y;
            Bs[lc4*4+2][r] = bv.z; Bs[lc4*4+3][r] = bv.w;
        }
        __syncthreads();
#pragma unroll
        for (int k = 0; k < 16; k++) {
            float4 a0 = *(const float4*)&As[k][ty << 3];
            float4 a1 = *(const float4*)&As[k][(ty << 3) + 4];
            float4 b0 = *(const float4*)&Bs[k][tx << 3];
            float4 b1 = *(const float4*)&Bs[k][(tx << 3) + 4];
            float ar[8] = {a0.x, a0.y, a0.z, a0.w, a1.x, a1.y, a1.z, a1.w};
            float br[8] = {b0.x, b0.y, b0.z, b0.w, b1.x, b1.y, b1.z, b1.w};
#pragma unroll
            for (int r = 0; r < 8; r++)
#pragma unroll
                for (int s = 0; s < 8; s++) acc[r][s] = fmaf(ar[r], br[s], acc[r][s]);
        }
        __syncthreads();
    }

    float nj[8];
#pragma unroll
    for (int s = 0; s < 8; s++) nj[s] = g_n2[(b << 10) + j0 + (tx << 3) + s];
#pragma unroll
    for (int r = 0; r < 8; r++) {
        int i = i0 + (ty << 3) + r;
        float ni = g_n2[(b << 10) + i];
        float4 o0, o1;
        o0.x = __fsub_rn(__fadd_rn(ni, nj[0]), __fmul_rn(2.0f, acc[r][0]));
        o0.y = __fsub_rn(__fadd_rn(ni, nj[1]), __fmul_rn(2.0f, acc[r][1]));
        o0.z = __fsub_rn(__fadd_rn(ni, nj[2]), __fmul_rn(2.0f, acc[r][2]));
        o0.w = __fsub_rn(__fadd_rn(ni, nj[3]), __fmul_rn(2.0f, acc[r][3]));
        o1.x = __fsub_rn(__fadd_rn(ni, nj[4]), __fmul_rn(2.0f, acc[r][4]));
        o1.y = __fsub_rn(__fadd_rn(ni, nj[5]), __fmul_rn(2.0f, acc[r][5]));
        o1.z = __fsub_rn(__fadd_rn(ni, nj[6]), __fmul_rn(2.0f, acc[r][6]));
        o1.w = __fsub_rn(__fadd_rn(ni, nj[7]), __fmul_rn(2.0f, acc[r][7]));
        size_t off = ((size_t)b << 20) + ((size_t)i << 10) + j0 + (tx << 3);
        *(float4*)&g_dist[off]     = o0;
        *(float4*)&g_dist[off + 4] = o1;
    }
}

// ---------------- Weff = WlA + (A-B)@WlB ; beff = b2@WlB -------------------------
__global__ __launch_bounds__(128) void prep_weff_kernel(
    const float* __restrict__ W2, const float* __restrict__ b2,
    const float* __restrict__ Wl) {
    int c = threadIdx.x;
    if (blockIdx.x < 64) {
        int d = blockIdx.x;
        float a0 = 0.f, a1 = 0.f, a2 = 0.f, a3 = 0.f;
        for (int e = 0; e < 128; e += 4) {
            a0 = fmaf(W2[d*128+e]   - W2[(64+d)*128+e],   Wl[(64+e)*128+c],   a0);
            a1 = fmaf(W2[d*128+e+1] - W2[(64+d)*128+e+1], Wl[(64+e+1)*128+c], a1);
            a2 = fmaf(W2[d*128+e+2] - W2[(64+d)*128+e+2], Wl[(64+e+2)*128+c], a2);
            a3 = fmaf(W2[d*128+e+3] - W2[(64+d)*128+e+3], Wl[(64+e+3)*128+c], a3);
        }
        g_Weff[d * 128 + c] = Wl[d * 128 + c] + ((a0 + a1) + (a2 + a3));
    } else {
        float a0 = 0.f, a1 = 0.f;
        for (int e = 0; e < 128; e += 2) {
            a0 = fmaf(b2[e],     Wl[(64+e)*128+c],   a0);
            a1 = fmaf(b2[e+1],   Wl[(64+e+1)*128+c], a1);
        }
        g_beff[c] = a0 + a1;
    }
}

// ---------------- EdgeConv2 v-branch: v2 = x1 @ W2[64:128] (8-pt staged) ---------
__global__ __launch_bounds__(256) void ec2_pre_kernel(const float* __restrict__ W2) {
    int c  = threadIdx.x & 127;
    int pg = threadIdx.x >> 7;   // 0 or 1
    float w[64];
#pragma unroll
    for (int d = 0; d < 64; d++) w[d] = W2[(64 + d) * 128 + c];

    __shared__ float xs[8][64];
    int p0 = blockIdx.x * 128;
    for (int r = 0; r < 16; r++) {
        int pb = p0 + r * 8;
#pragma unroll
        for (int s = 0; s < 2; s++) {
            int q = threadIdx.x + s * 256;
            xs[q >> 6][q & 63] = g_x1[(size_t)(pb + (q >> 6)) * 64 + (q & 63)];
        }
        __syncthreads();
#pragma unroll
        for (int pp = 0; pp < 4; pp++) {
            int p = pg + pp * 2;
            float y0 = 0.f, y1 = 0.f, y2 = 0.f, y3 = 0.f;
#pragma unroll
            for (int d = 0; d < 64; d += 16) {
                float4 q0 = *(const float4*)&xs[p][d];
                float4 q1 = *(const float4*)&xs[p][d + 4];
                float4 q2 = *(const float4*)&xs[p][d + 8];
                float4 q3 = *(const float4*)&xs[p][d + 12];
                y0 = fmaf(q0.x, w[d],    y0); y0 = fmaf(q0.y, w[d+1],  y0);
                y0 = fmaf(q0.z, w[d+2],  y0); y0 = fmaf(q0.w, w[d+3],  y0);
                y1 = fmaf(q1.x, w[d+4],  y1); y1 = fmaf(q1.y, w[d+5],  y1);
                y1 = fmaf(q1.z, w[d+6],  y1); y1 = fmaf(q1.w, w[d+7],  y1);
                y2 = fmaf(q2.x, w[d+8],  y2); y2 = fmaf(q2.y, w[d+9],  y2);
                y2 = fmaf(q2.z, w[d+10], y2); y2 = fmaf(q2.w, w[d+11], y2);
                y3 = fmaf(q3.x, w[d+12], y3); y3 = fmaf(q3.y, w[d+13], y3);
                y3 = fmaf(q3.z, w[d+14], y3); y3 = fmaf(q3.w, w[d+15], y3);
            }
            g_v2[(size_t)(pb + p) * 128 + c] = (y0 + y1) + (y2 + y3);
        }
        __syncthreads();
    }
}

// ---------------- EdgeConv2 neighbor max: m = max_k v2[nbr] (float4) -------------
__global__ __launch_bounds__(256) void ec2_combine_kernel() {
    int t = blockIdx.x * 256 + threadIdx.x;   // NPT*32 threads
    int i  = t >> 5;
    int c4 = (t & 31) << 2;
    int base = (i >> 10) << 10;
    int id[KNN];
#pragma unroll
    for (int k = 0; k < KNN; k++) id[k] = g_idx[i * KNN + k];
    float4 m = make_float4(-FLT_MAX, -FLT_MAX, -FLT_MAX, -FLT_MAX);
#pragma unroll
    for (int k = 0; k < KNN; k++) {
        float4 v = *(const float4*)&g_v2[(size_t)(base + id[k]) * 128 + c4];
        m.x = fmaxf(m.x, v.x); m.y = fmaxf(m.y, v.y);
        m.z = fmaxf(m.z, v.z); m.w = fmaxf(m.w, v.w);
    }
    *(float4*)&g_m[(size_t)i * 128 + c4] = m;
}

// ---------------- fused final linear + running global max pool -------------------
__global__ __launch_bounds__(384) void finpool_kernel(const float* __restrict__ Wl) {
    int tid = threadIdx.x;
    int g = tid / 128;       // 0,1,2 (k-chunk group)
    int c = tid % 128;

    float w[64];
    if (g == 0) {
#pragma unroll
        for (int d = 0; d < 64; d++) w[d] = g_Weff[d * 128 + c];
    } else if (g == 1) {
#pragma unroll
        for (int d = 0; d < 64; d++) w[d] = Wl[(64 + d) * 128 + c];
    } else {
#pragma unroll
        for (int d = 0; d < 64; d++) w[d] = Wl[(128 + d) * 128 + c];
    }
    int off = (g == 0) ? 0 : ((g == 1) ? 64 : 128);

    __shared__ float xs[4][192];
    __shared__ float ps[3][4][128];
    float rm = -FLT_MAX;
    int p0 = blockIdx.x * 256;

    for (int r = 0; r < 64; r++) {
        int pb = p0 + r * 4;
#pragma unroll
        for (int s = 0; s < 2; s++) {
            int q = tid + s * 384;
            int p = q / 192, e = q % 192;
            xs[p][e] = (e < 64) ? g_x1[(size_t)(pb + p) * 64 + e]
                                : g_m[(size_t)(pb + p) * 128 + (e - 64)];
        }
        __syncthreads();
#pragma unroll
        for (int p = 0; p < 4; p++) {
            float y0 = 0.f, y1 = 0.f, y2 = 0.f, y3 = 0.f;
#pragma unroll
            for (int d = 0; d < 64; d += 16) {
                float4 q0 = *(const float4*)&xs[p][off + d];
                float4 q1 = *(const float4*)&xs[p][off + d + 4];
                float4 q2 = *(const float4*)&xs[p][off + d + 8];
                float4 q3 = *(const float4*)&xs[p][off + d + 12];
                y0 = fmaf(q0.x, w[d],    y0); y0 = fmaf(q0.y, w[d+1],  y0);
                y0 = fmaf(q0.z, w[d+2],  y0); y0 = fmaf(q0.w, w[d+3],  y0);
                y1 = fmaf(q1.x, w[d+4],  y1); y1 = fmaf(q1.y, w[d+5],  y1);
                y1 = fmaf(q1.z, w[d+6],  y1); y1 = fmaf(q1.w, w[d+7],  y1);
                y2 = fmaf(q2.x, w[d+8],  y2); y2 = fmaf(q2.y, w[d+9],  y2);
                y2 = fmaf(q2.z, w[d+10], y2); y2 = fmaf(q2.w, w[d+11], y2);
                y3 = fmaf(q3.x, w[d+12], y3); y3 = fmaf(q3.y, w[d+13], y3);
                y3 = fmaf(q3.z, w[d+14], y3); y3 = fmaf(q3.w, w[d+15], y3);
            }
            ps[g][p][c] = (y0 + y1) + (y2 + y3);
        }
        __syncthreads();
        if (g == 0) {
#pragma unroll
            for (int p = 0; p < 4; p++)
                rm = fmaxf(rm, ps[0][p][c] + ps[1][p][c] + ps[2][p][c]);
        }
    }
    if (g == 0) g_part[blockIdx.x * 128 + c] = rm;
}

// ---------------- final reduce over 4 segments per cloud -------------------------
__global__ void pool2_kernel(const float* __restrict__ bl, float* __restrict__ out) {
    int b = blockIdx.x;       // 32
    int c = threadIdx.x;      // 128
    float m = -FLT_MAX;
#pragma unroll
    for (int s = 0; s < 4; s++) m = fmaxf(m, g_part[(b * 4 + s) * 128 + c]);
    out[b * 128 + c] = m + g_beff[c] + bl[c];
}

// ---------------- launch --------------------------------------------------------
extern "C" void kernel_launch(void* const* d_in, const int* in_sizes, int n_in,
                              void* d_out, int out_size) {
    const float* pos = (const float*)d_in[0];
    const float* W1a = (const float*)d_in[1];
    const float* b1a = (const float*)d_in[2];
    const float* g1  = (const float*)d_in[3];
    const float* be1 = (const float*)d_in[4];
    const float* W1b = (const float*)d_in[5];
    const float* b1b = (const float*)d_in[6];
    const float* W2  = (const float*)d_in[7];
    const float* b2  = (const float*)d_in[8];
    const float* Wl  = (const float*)d_in[9];
    const float* bl  = (const float*)d_in[10];
    float* out = (float*)d_out;

    // knn on pos (fused dist + top-k + ec1_pre)
    knn1_kernel<<<2048, 512>>>(pos, W1a, b1a);

    // EdgeConv1 — ec1_apply deliberately placed as the 4th launch (ncu captures #4)
    ec1_stats_kernel<<<STATS_BLOCKS, 256>>>();
    ec1_bn_kernel<<<1, 1024>>>(g1, be1);
    ec1_apply_kernel<<<NPT / 4, 256>>>(W1b, b1b);   // + fused n2

    prep_weff_kernel<<<65, 128>>>(W2, b2, Wl);      // independent of point data

    // knn on x1
    gram_kernel<<<dim3(8, 8, BATCH), 256>>>();
    topk_kernel<<<NPT / 8, 256>>>();

    // EdgeConv2 (v-branch only; u-branch folded into Weff)
    ec2_pre_kernel<<<256, 256>>>(W2);
    ec2_combine_kernel<<<NPT * 32 / 256, 256>>>();

    // fused final linear + pool
    finpool_kernel<<<128, 384>>>(Wl);
    pool2_kernel<<<BATCH, 128>>>(bl, out);
}

// round 8
// speedup vs baseline: 1.6800x; 1.0012x over previous
#include <cuda_runtime.h>
#include <float.h>

#define BATCH 32
#define PTS   1024
#define NPT   (BATCH*PTS)     // 32768
#define KNN   20
#define EDGES (NPT*KNN)       // 655360
#define STATS_BLOCKS 1024
#define KEY_MAX 0xFFFFFFFFFFFFFFFFull

// ---------------- packed f32x2 helpers (Blackwell 2x fp32) -----------------------
__device__ __forceinline__ void fma2(unsigned long long &y, unsigned long long a,
                                     unsigned long long b) {
    asm("fma.rn.f32x2 %0, %1, %2, %0;" : "+l"(y) : "l"(a), "l"(b));
}
__device__ __forceinline__ unsigned long long pk2(float lo, float hi) {
    unsigned long long r;
    asm("mov.b64 %0, {%1, %2};" : "=l"(r) : "f"(lo), "f"(hi));
    return r;
}
__device__ __forceinline__ float2 upk2(unsigned long long v) {
    float2 f;
    asm("mov.b64 {%0, %1}, %2;" : "=f"(f.x), "=f"(f.y) : "l"(v));
    return f;
}

// ---------------- scratch (static device globals; no allocation) ----------------
__device__ float g_dist[(size_t)BATCH*PTS*PTS];   // 128 MB (knn2 only)
__device__ int   g_idx[NPT*KNN];
__device__ float g_u1[NPT*64];
__device__ float g_v1[NPT*64];
__device__ float g_x1[NPT*64];
__device__ float g_n2[NPT];
__device__ float g_part[STATS_BLOCKS*128];        // stats partials / pool partials
__device__ float g_scale[64];
__device__ float g_shift[64];
__device__ float g_v2[NPT*128];
__device__ float g_m[NPT*128];
__device__ float g_Weff[64*128];
__device__ float g_beff[128];

// ---------------- u64-key top-k: key = monotonic(dist) << 32 | j -----------------
__device__ __forceinline__ unsigned long long fkey(float v, int j) {
    unsigned int b = __float_as_uint(v);
    b = (b & 0x80000000u) ? ~b : (b | 0x80000000u);   // total order on floats
    return ((unsigned long long)b << 32) | (unsigned int)j;
}

__device__ __forceinline__ void kinsert64(unsigned long long k,
                                          unsigned long long (&keys)[KNN]) {
    if (k < keys[KNN-1]) {
        int pos = KNN - 1;
#pragma unroll
        for (int t = KNN - 2; t >= 0; t--)
            if (k < keys[t]) pos = t;
#pragma unroll
        for (int t = KNN - 1; t >= 0; t--) {
            if (t > pos)       keys[t] = keys[t-1];
            else if (t == pos) keys[t] = k;
        }
    }
}

__device__ __forceinline__ void kmerge_write64(unsigned long long (&keys)[KNN], int row) {
    int lane = threadIdx.x & 31;
    for (int r = 0; r < KNN; r++) {
        unsigned long long ck = keys[0];
#pragma unroll
        for (int o = 16; o > 0; o >>= 1) {
            unsigned long long ok = __shfl_xor_sync(0xffffffffu, ck, o);
            if (ok < ck) ck = ok;
        }
        if (lane == 0) g_idx[row * KNN + r] = (int)(unsigned int)(ck & 0xFFFFFFFFull);
        if (keys[0] == ck) {
#pragma unroll
            for (int t = 0; t < KNN - 1; t++) keys[t] = keys[t+1];
            keys[KNN-1] = KEY_MAX;
        }
    }
}

// ---------------- knn1 fused: dist-on-the-fly + top-20 + ec1_pre ----------------
__global__ __launch_bounds__(512) void knn1_kernel(
    const float* __restrict__ pos, const float* __restrict__ W1a,
    const float* __restrict__ b1a) {
    __shared__ __align__(16) float4 sp[PTS];   // 16 KB: {x,y,z,d2}
    __shared__ float sw[384];
    __shared__ float sb[64];
    int cloud  = blockIdx.x >> 6;      // 64 blocks per cloud, 16 rows per block
    int rowblk = blockIdx.x & 63;
    const float* pb = pos + (size_t)cloud * PTS * 3;
    for (int p = threadIdx.x; p < PTS; p += 512) {
        float x = pb[p*3], y = pb[p*3+1], z = pb[p*3+2];
        float d2 = __fadd_rn(__fadd_rn(__fmul_rn(x,x), __fmul_rn(y,y)), __fmul_rn(z,z));
        sp[p] = make_float4(x, y, z, d2);
    }
    for (int t = threadIdx.x; t < 384; t += 512) sw[t] = W1a[t];
    if (threadIdx.x < 64) sb[threadIdx.x] = b1a[threadIdx.x];
    __syncthreads();

    int warp = threadIdx.x >> 5, lane = threadIdx.x & 31;
    int il = rowblk * 16 + warp;
    float4 q = sp[il];

    unsigned long long keys[KNN];
#pragma unroll
    for (int t = 0; t < KNN; t++) keys[t] = KEY_MAX;

    for (int t = 0; t < 32; t++) {
        int j = t * 32 + lane;
        float4 p = sp[j];
        float dot = __fadd_rn(__fadd_rn(__fmul_rn(q.x,p.x), __fmul_rn(q.y,p.y)), __fmul_rn(q.z,p.z));
        float v = __fsub_rn(__fadd_rn(q.w, p.w), __fmul_rn(2.0f, dot));
        kinsert64(fkey(v, j), keys);
    }
    kmerge_write64(keys, cloud * PTS + il);

    // fused ec1_pre: u = x@(A-B)+b1a, v = x@B for this block's 16 points
    int c = threadIdx.x & 63;
#pragma unroll
    for (int rep = 0; rep < 2; rep++) {
        int pl  = (threadIdx.x >> 6) + rep * 8;
        int il2 = rowblk * 16 + pl;
        float4 P = sp[il2];
        float a  = P.x * sw[c]       + P.y * sw[64 + c]  + P.z * sw[128 + c];
        float bb = P.x * sw[192 + c] + P.y * sw[256 + c] + P.z * sw[320 + c];
        int gp = ((cloud << 10) + il2) * 64 + c;
        g_u1[gp] = a - bb + sb[c];
        g_v1[gp] = bb;
    }
}

// ---------------- knn2 top-k (reads g_dist, float4 per lane) ---------------------
__global__ __launch_bounds__(256) void topk_kernel() {
    int warp = (blockIdx.x * blockDim.x + threadIdx.x) >> 5;
    int lane = threadIdx.x & 31;
    if (warp >= NPT) return;
    const float4* row = (const float4*)(g_dist + ((size_t)warp << 10));

    unsigned long long keys[KNN];
#pragma unroll
    for (int t = 0; t < KNN; t++) keys[t] = KEY_MAX;
#pragma unroll
    for (int t = 0; t < 8; t++) {
        int e = t * 32 + lane;
        float4 v = row[e];
        int j = e << 2;
        kinsert64(fkey(v.x, j),     keys);
        kinsert64(fkey(v.y, j + 1), keys);
        kinsert64(fkey(v.z, j + 2), keys);
        kinsert64(fkey(v.w, j + 3), keys);
    }
    kmerge_write64(keys, warp);
}

// ---------------- BN stats: per-point algebraic fold -----------------------------
__global__ __launch_bounds__(256) void ec1_stats_kernel() {
    int c  = threadIdx.x & 63;
    int sl = threadIdx.x >> 6;   // 0..3
    int p0 = blockIdx.x * 32;    // 1024 blocks x 32 points
    float s = 0.f, s2 = 0.f;
    for (int pp = sl; pp < 32; pp += 4) {
        int p = p0 + pp;
        int base = (p >> 10) << 10;
        float u = g_u1[p * 64 + c];
        int id[KNN];
#pragma unroll
        for (int k = 0; k < KNN; k++) id[k] = g_idx[p * KNN + k];
        float S = 0.f, T = 0.f;
#pragma unroll
        for (int k = 0; k < KNN; k++) {
            float v = g_v1[(base + id[k]) * 64 + c];
            S += v;
            T = fmaf(v, v, T);
        }
        s  += fmaf(20.0f, u, S);
        s2 += fmaf(u, fmaf(20.0f, u, 2.0f * S), T);
    }
    __shared__ float sh[2][4][64];
    sh[0][sl][c] = s; sh[1][sl][c] = s2;
    __syncthreads();
    if (sl == 0) {
        float ts = sh[0][0][c] + sh[0][1][c] + sh[0][2][c] + sh[0][3][c];
        float t2 = sh[1][0][c] + sh[1][1][c] + sh[1][2][c] + sh[1][3][c];
        g_part[blockIdx.x * 128 + c]      = ts;
        g_part[blockIdx.x * 128 + 64 + c] = t2;
    }
}

// ---------------- BN finalize (16-way partials) -----------------------------------
__global__ __launch_bounds__(1024) void ec1_bn_kernel(
    const float* __restrict__ g1, const float* __restrict__ be1) {
    int c = threadIdx.x & 63;
    int g = threadIdx.x >> 6;    // 0..15
    float s = 0.f, s2 = 0.f;
    for (int b = g; b < STATS_BLOCKS; b += 16) {
        s  += g_part[b * 128 + c];
        s2 += g_part[b * 128 + 64 + c];
    }
    __shared__ float sh[16][64], sh2[16][64];
    sh[g][c] = s; sh2[g][c] = s2;
    __syncthreads();
    if (g == 0) {
        float ts = 0.f, t2 = 0.f;
#pragma unroll
        for (int r = 0; r < 16; r++) { ts += sh[r][c]; t2 += sh2[r][c]; }
        float n   = (float)EDGES;
        float mu  = ts / n;
        float var = t2 / n - mu * mu;
        float sc  = g1[c] * rsqrtf(var + 1e-5f);
        g_scale[c] = sc;
        g_shift[c] = be1[c] - mu * sc;
    }
}

// ---------------- EdgeConv1 apply: stage 20 relu'd edges, f32x2 GEMV, max; + n2 --
__global__ __launch_bounds__(256) void ec1_apply_kernel(
    const float* __restrict__ W1b, const float* __restrict__ b1b) {
    int pt = threadIdx.x >> 6;     // 4 points per block
    int c  = threadIdx.x & 63;
    int i  = blockIdx.x * 4 + pt;

    unsigned long long w2[32];
#pragma unroll
    for (int d = 0; d < 32; d++)
        w2[d] = pk2(W1b[(2*d) * 64 + c], W1b[(2*d+1) * 64 + c]);

    __shared__ __align__(16) float hb[4][KNN][64];
    float sc  = g_scale[c], shv = g_shift[c];
    float a   = fmaf(g_u1[i * 64 + c], sc, shv);
    int  base = (i >> 10) << 10;

    int id[KNN];
#pragma unroll
    for (int k = 0; k < KNN; k++) id[k] = g_idx[i * KNN + k];
#pragma unroll
    for (int k = 0; k < KNN; k++)
        hb[pt][k][c] = fmaxf(fmaf(g_v1[(base + id[k]) * 64 + c], sc, a), 0.0f);
    __syncthreads();

    float bb  = b1b[c];
    float acc = -FLT_MAX;
#pragma unroll
    for (int k = 0; k < KNN; k++) {
        unsigned long long Y0 = 0ull, Y1 = 0ull, Y2 = 0ull, Y3 = 0ull;
        const ulonglong2* hp = (const ulonglong2*)&hb[pt][k][0];
#pragma unroll
        for (int i4 = 0; i4 < 16; i4 += 4) {
            ulonglong2 q0 = hp[i4];
            ulonglong2 q1 = hp[i4 + 1];
            ulonglong2 q2 = hp[i4 + 2];
            ulonglong2 q3 = hp[i4 + 3];
            fma2(Y0, q0.x, w2[2*i4]);     fma2(Y1, q0.y, w2[2*i4 + 1]);
            fma2(Y2, q1.x, w2[2*i4 + 2]); fma2(Y3, q1.y, w2[2*i4 + 3]);
            fma2(Y0, q2.x, w2[2*i4 + 4]); fma2(Y1, q2.y, w2[2*i4 + 5]);
            fma2(Y2, q3.x, w2[2*i4 + 6]); fma2(Y3, q3.y, w2[2*i4 + 7]);
        }
        float2 f0 = upk2(Y0), f1 = upk2(Y1), f2 = upk2(Y2), f3 = upk2(Y3);
        float y = ((f0.x + f0.y) + (f1.x + f1.y)) + (((f2.x + f2.y) + (f3.x + f3.y)) + bb);
        acc = fmaxf(acc, y);
    }
    g_x1[i * 64 + c] = acc;

    // fused n2: squared norm per point
    __shared__ float nsq[4][64];
    __shared__ float npart[4][8];
    nsq[pt][c] = acc * acc;
    __syncthreads();
    if (c < 8) {
        float s = 0.f;
#pragma unroll
        for (int m = 0; m < 8; m++) s += nsq[pt][c * 8 + m];
        npart[pt][c] = s;
    }
    __syncthreads();
    if (c == 0) {
        float s = 0.f;
#pragma unroll
        for (int m = 0; m < 8; m++) s += npart[pt][m];
        g_n2[i] = s;
    }
}

// ---------------- knn2: Gram GEMM, 128x128 tile / 8x8 microtile, f32x2 -----------
__global__ __launch_bounds__(256) void gram_kernel() {
    int b  = blockIdx.z;
    int i0 = blockIdx.y << 7;
    int j0 = blockIdx.x << 7;
    const float* xb = g_x1 + ((size_t)b << 10) * 64;

    __shared__ __align__(16) float As[16][132];
    __shared__ __align__(16) float Bs[16][132];

    int tid = threadIdx.x;
    int tx = tid & 15, ty = tid >> 4;
    int lr = tid >> 2, lc4 = tid & 3;

    unsigned long long ACC[8][4];   // packed pairs over s
#pragma unroll
    for (int r = 0; r < 8; r++)
#pragma unroll
        for (int s = 0; s < 4; s++) ACC[r][s] = 0ull;

    for (int k0 = 0; k0 < 64; k0 += 16) {
#pragma unroll
        for (int half = 0; half < 2; half++) {
            int r = lr + half * 64;
            float4 av = *(const float4*)&xb[(i0 + r) * 64 + k0 + lc4 * 4];
            float4 bv = *(const float4*)&xb[(j0 + r) * 64 + k0 + lc4 * 4];
            As[lc4*4+0][r] = av.x; As[lc4*4+1][r] = av.y;
            As[lc4*4+2][r] = av.z; As[lc4*4+3][r] = av.w;
            Bs[lc4*4+0][r] = bv.x; Bs[lc4*4+1][r] = bv.y;
            Bs[lc4*4+2][r] = bv.z; Bs[lc4*4+3][r] = bv.w;
        }
        __syncthreads();
#pragma unroll
        for (int k = 0; k < 16; k++) {
            float4 a0 = *(const float4*)&As[k][ty << 3];
            float4 a1 = *(const float4*)&As[k][(ty << 3) + 4];
            ulonglong2 B0 = *(const ulonglong2*)&Bs[k][tx << 3];
            ulonglong2 B1 = *(const ulonglong2*)&Bs[k][(tx << 3) + 4];
            unsigned long long A[8];
            A[0] = pk2(a0.x, a0.x); A[1] = pk2(a0.y, a0.y);
            A[2] = pk2(a0.z, a0.z); A[3] = pk2(a0.w, a0.w);
            A[4] = pk2(a1.x, a1.x); A[5] = pk2(a1.y, a1.y);
            A[6] = pk2(a1.z, a1.z); A[7] = pk2(a1.w, a1.w);
#pragma unroll
            for (int r = 0; r < 8; r++) {
                fma2(ACC[r][0], A[r], B0.x);
                fma2(ACC[r][1], A[r], B0.y);
                fma2(ACC[r][2], A[r], B1.x);
                fma2(ACC[r][3], A[r], B1.y);
            }
        }
        __syncthreads();
    }

    float nj[8];
#pragma unroll
    for (int s = 0; s < 8; s++) nj[s] = g_n2[(b << 10) + j0 + (tx << 3) + s];
#pragma unroll
    for (int r = 0; r < 8; r++) {
        int i = i0 + (ty << 3) + r;
        float ni = g_n2[(b << 10) + i];
        float2 c0 = upk2(ACC[r][0]), c1 = upk2(ACC[r][1]);
        float2 c2 = upk2(ACC[r][2]), c3 = upk2(ACC[r][3]);
        float4 o0, o1;
        o0.x = __fsub_rn(__fadd_rn(ni, nj[0]), __fmul_rn(2.0f, c0.x));
        o0.y = __fsub_rn(__fadd_rn(ni, nj[1]), __fmul_rn(2.0f, c0.y));
        o0.z = __fsub_rn(__fadd_rn(ni, nj[2]), __fmul_rn(2.0f, c1.x));
        o0.w = __fsub_rn(__fadd_rn(ni, nj[3]), __fmul_rn(2.0f, c1.y));
        o1.x = __fsub_rn(__fadd_rn(ni, nj[4]), __fmul_rn(2.0f, c2.x));
        o1.y = __fsub_rn(__fadd_rn(ni, nj[5]), __fmul_rn(2.0f, c2.y));
        o1.z = __fsub_rn(__fadd_rn(ni, nj[6]), __fmul_rn(2.0f, c3.x));
        o1.w = __fsub_rn(__fadd_rn(ni, nj[7]), __fmul_rn(2.0f, c3.y));
        size_t off = ((size_t)b << 20) + ((size_t)i << 10) + j0 + (tx << 3);
        *(float4*)&g_dist[off]     = o0;
        *(float4*)&g_dist[off + 4] = o1;
    }
}

// ---------------- Weff = WlA + (A-B)@WlB ; beff = b2@WlB -------------------------
__global__ __launch_bounds__(128) void prep_weff_kernel(
    const float* __restrict__ W2, const float* __restrict__ b2,
    const float* __restrict__ Wl) {
    int c = threadIdx.x;
    if (blockIdx.x < 64) {
        int d = blockIdx.x;
        float a0 = 0.f, a1 = 0.f, a2 = 0.f, a3 = 0.f;
        for (int e = 0; e < 128; e += 4) {
            a0 = fmaf(W2[d*128+e]   - W2[(64+d)*128+e],   Wl[(64+e)*128+c],   a0);
            a1 = fmaf(W2[d*128+e+1] - W2[(64+d)*128+e+1], Wl[(64+e+1)*128+c], a1);
            a2 = fmaf(W2[d*128+e+2] - W2[(64+d)*128+e+2], Wl[(64+e+2)*128+c], a2);
            a3 = fmaf(W2[d*128+e+3] - W2[(64+d)*128+e+3], Wl[(64+e+3)*128+c], a3);
        }
        g_Weff[d * 128 + c] = Wl[d * 128 + c] + ((a0 + a1) + (a2 + a3));
    } else {
        float a0 = 0.f, a1 = 0.f;
        for (int e = 0; e < 128; e += 2) {
            a0 = fmaf(b2[e],     Wl[(64+e)*128+c],   a0);
            a1 = fmaf(b2[e+1],   Wl[(64+e+1)*128+c], a1);
        }
        g_beff[c] = a0 + a1;
    }
}

// ---------------- EdgeConv2 v-branch: v2 = x1 @ W2[64:128], f32x2 ----------------
__global__ __launch_bounds__(256) void ec2_pre_kernel(const float* __restrict__ W2) {
    int c  = threadIdx.x & 127;
    int pg = threadIdx.x >> 7;   // 0 or 1
    unsigned long long w2[32];
#pragma unroll
    for (int d = 0; d < 32; d++)
        w2[d] = pk2(W2[(64 + 2*d) * 128 + c], W2[(64 + 2*d+1) * 128 + c]);

    __shared__ __align__(16) float xs[8][64];
    int p0 = blockIdx.x * 128;
    for (int r = 0; r < 16; r++) {
        int pb = p0 + r * 8;
#pragma unroll
        for (int s = 0; s < 2; s++) {
            int q = threadIdx.x + s * 256;
            xs[q >> 6][q & 63] = g_x1[(size_t)(pb + (q >> 6)) * 64 + (q & 63)];
        }
        __syncthreads();
#pragma unroll
        for (int pp = 0; pp < 4; pp++) {
            int p = pg + pp * 2;
            unsigned long long Y0 = 0ull, Y1 = 0ull, Y2 = 0ull, Y3 = 0ull;
            const ulonglong2* xp = (const ulonglong2*)&xs[p][0];
#pragma unroll
            for (int i4 = 0; i4 < 16; i4 += 4) {
                ulonglong2 q0 = xp[i4];
                ulonglong2 q1 = xp[i4 + 1];
                ulonglong2 q2 = xp[i4 + 2];
                ulonglong2 q3 = xp[i4 + 3];
                fma2(Y0, q0.x, w2[2*i4]);     fma2(Y1, q0.y, w2[2*i4 + 1]);
                fma2(Y2, q1.x, w2[2*i4 + 2]); fma2(Y3, q1.y, w2[2*i4 + 3]);
                fma2(Y0, q2.x, w2[2*i4 + 4]); fma2(Y1, q2.y, w2[2*i4 + 5]);
                fma2(Y2, q3.x, w2[2*i4 + 6]); fma2(Y3, q3.y, w2[2*i4 + 7]);
            }
            float2 f0 = upk2(Y0), f1 = upk2(Y1), f2 = upk2(Y2), f3 = upk2(Y3);
            g_v2[(size_t)(pb + p) * 128 + c] =
                ((f0.x + f0.y) + (f1.x + f1.y)) + ((f2.x + f2.y) + (f3.x + f3.y));
        }
        __syncthreads();
    }
}

// ---------------- EdgeConv2 neighbor max: m = max_k v2[nbr] (float4) -------------
__global__ __launch_bounds__(256) void ec2_combine_kernel() {
    int t = blockIdx.x * 256 + threadIdx.x;   // NPT*32 threads
    int i  = t >> 5;
    int c4 = (t & 31) << 2;
    int base = (i >> 10) << 10;
    int id[KNN];
#pragma unroll
    for (int k = 0; k < KNN; k++) id[k] = g_idx[i * KNN + k];
    float4 m = make_float4(-FLT_MAX, -FLT_MAX, -FLT_MAX, -FLT_MAX);
#pragma unroll
    for (int k = 0; k < KNN; k++) {
        float4 v = *(const float4*)&g_v2[(size_t)(base + id[k]) * 128 + c4];
        m.x = fmaxf(m.x, v.x); m.y = fmaxf(m.y, v.y);
        m.z = fmaxf(m.z, v.z); m.w = fmaxf(m.w, v.w);
    }
    *(float4*)&g_m[(size_t)i * 128 + c4] = m;
}

// ---------------- fused final linear + running global max pool, f32x2 ------------
__global__ __launch_bounds__(384) void finpool_kernel(const float* __restrict__ Wl) {
    int tid = threadIdx.x;
    int g = tid / 128;       // 0,1,2 (k-chunk group)
    int c = tid % 128;

    unsigned long long w2[32];
    if (g == 0) {
#pragma unroll
        for (int d = 0; d < 32; d++)
            w2[d] = pk2(g_Weff[(2*d) * 128 + c], g_Weff[(2*d+1) * 128 + c]);
    } else if (g == 1) {
#pragma unroll
        for (int d = 0; d < 32; d++)
            w2[d] = pk2(Wl[(64 + 2*d) * 128 + c], Wl[(64 + 2*d+1) * 128 + c]);
    } else {
#pragma unroll
        for (int d = 0; d < 32; d++)
            w2[d] = pk2(Wl[(128 + 2*d) * 128 + c], Wl[(128 + 2*d+1) * 128 + c]);
    }
    int off = (g == 0) ? 0 : ((g == 1) ? 64 : 128);

    __shared__ __align__(16) float xs[4][192];
    __shared__ float ps[3][4][128];
    float rm = -FLT_MAX;
    int p0 = blockIdx.x * 256;

    for (int r = 0; r < 64; r++) {
        int pb = p0 + r * 4;
#pragma unroll
        for (int s = 0; s < 2; s++) {
            int q = tid + s * 384;
            int p = q / 192, e = q % 192;
            xs[p][e] = (e < 64) ? g_x1[(size_t)(pb + p) * 64 + e]
                                : g_m[(size_t)(pb + p) * 128 + (e - 64)];
        }
        __syncthreads();
#pragma unroll
        for (int p = 0; p < 4; p++) {
            unsigned long long Y0 = 0ull, Y1 = 0ull, Y2 = 0ull, Y3 = 0ull;
            const ulonglong2* xp = (const ulonglong2*)&xs[p][off];
#pragma unroll
            for (int i4 = 0; i4 < 16; i4 += 4) {
                ulonglong2 q0 = xp[i4];
                ulonglong2 q1 = xp[i4 + 1];
                ulonglong2 q2 = xp[i4 + 2];
                ulonglong2 q3 = xp[i4 + 3];
                fma2(Y0, q0.x, w2[2*i4]);     fma2(Y1, q0.y, w2[2*i4 + 1]);
                fma2(Y2, q1.x, w2[2*i4 + 2]); fma2(Y3, q1.y, w2[2*i4 + 3]);
                fma2(Y0, q2.x, w2[2*i4 + 4]); fma2(Y1, q2.y, w2[2*i4 + 5]);
                fma2(Y2, q3.x, w2[2*i4 + 6]); fma2(Y3, q3.y, w2[2*i4 + 7]);
            }
            float2 f0 = upk2(Y0), f1 = upk2(Y1), f2 = upk2(Y2), f3 = upk2(Y3);
            ps[g][p][c] = ((f0.x + f0.y) + (f1.x + f1.y)) + ((f2.x + f2.y) + (f3.x + f3.y));
        }
        __syncthreads();
        if (g == 0) {
#pragma unroll
            for (int p = 0; p < 4; p++)
                rm = fmaxf(rm, ps[0][p][c] + ps[1][p][c] + ps[2][p][c]);
        }
    }
    if (g == 0) g_part[blockIdx.x * 128 + c] = rm;
}

// ---------------- final reduce over 4 segments per cloud -------------------------
__global__ void pool2_kernel(const float* __restrict__ bl, float* __restrict__ out) {
    int b = blockIdx.x;       // 32
    int c = threadIdx.x;      // 128
    float m = -FLT_MAX;
#pragma unroll
    for (int s = 0; s < 4; s++) m = fmaxf(m, g_part[(b * 4 + s) * 128 + c]);
    out[b * 128 + c] = m + g_beff[c] + bl[c];
}

// ---------------- launch --------------------------------------------------------
extern "C" void kernel_launch(void* const* d_in, const int* in_sizes, int n_in,
                              void* d_out, int out_size) {
    const float* pos = (const float*)d_in[0];
    const float* W1a = (const float*)d_in[1];
    const float* b1a = (const float*)d_in[2];
    const float* g1  = (const float*)d_in[3];
    const float* be1 = (const float*)d_in[4];
    const float* W1b = (const float*)d_in[5];
    const float* b1b = (const float*)d_in[6];
    const float* W2  = (const float*)d_in[7];
    const float* b2  = (const float*)d_in[8];
    const float* Wl  = (const float*)d_in[9];
    const float* bl  = (const float*)d_in[10];
    float* out = (float*)d_out;

    // knn on pos (fused dist + top-k + ec1_pre)
    knn1_kernel<<<2048, 512>>>(pos, W1a, b1a);

    // EdgeConv1 — ec1_apply deliberately kept as the 4th launch (ncu captures #4)
    ec1_stats_kernel<<<STATS_BLOCKS, 256>>>();
    ec1_bn_kernel<<<1, 1024>>>(g1, be1);
    ec1_apply_kernel<<<NPT / 4, 256>>>(W1b, b1b);   // + fused n2

    prep_weff_kernel<<<65, 128>>>(W2, b2, Wl);      // independent of point data

    // knn on x1
    gram_kernel<<<dim3(8, 8, BATCH), 256>>>();
    topk_kernel<<<NPT / 8, 256>>>();

    // EdgeConv2 (v-branch only; u-branch folded into Weff)
    ec2_pre_kernel<<<256, 256>>>(W2);
    ec2_combine_kernel<<<NPT * 32 / 256, 256>>>();

    // fused final linear + pool
    finpool_kernel<<<128, 384>>>(Wl);
    pool2_kernel<<<BATCH, 128>>>(bl, out);
}

// round 9
// speedup vs baseline: 1.7621x; 1.0489x over previous
#include <cuda_runtime.h>
#include <float.h>

#define BATCH 32
#define PTS   1024
#define NPT   (BATCH*PTS)     // 32768
#define KNN   20
#define EDGES (NPT*KNN)       // 655360
#define STATS_BLOCKS 1024
#define KEY_MAX 0xFFFFFFFFFFFFFFFFull

// ---------------- packed f32x2 helpers (Blackwell 2x fp32) -----------------------
__device__ __forceinline__ void fma2(unsigned long long &y, unsigned long long a,
                                     unsigned long long b) {
    asm("fma.rn.f32x2 %0, %1, %2, %0;" : "+l"(y) : "l"(a), "l"(b));
}
__device__ __forceinline__ unsigned long long pk2(float lo, float hi) {
    unsigned long long r;
    asm("mov.b64 %0, {%1, %2};" : "=l"(r) : "f"(lo), "f"(hi));
    return r;
}
__device__ __forceinline__ float2 upk2(unsigned long long v) {
    float2 f;
    asm("mov.b64 {%0, %1}, %2;" : "=f"(f.x), "=f"(f.y) : "l"(v));
    return f;
}

// ---------------- scratch (static device globals; no allocation) ----------------
__device__ float g_dist[(size_t)BATCH*PTS*PTS];   // 128 MB (knn2 only)
__device__ int   g_idx[NPT*KNN];
__device__ float g_u1[NPT*64];
__device__ float g_v1[NPT*64];
__device__ float g_x1[NPT*64];
__device__ float g_n2[NPT];
__device__ float g_part[STATS_BLOCKS*128];        // stats partials / pool partials
__device__ float g_scale[64];
__device__ float g_shift[64];
__device__ float g_v2[NPT*128];
__device__ float g_m[NPT*128];
__device__ float g_Weff[64*128];
__device__ float g_beff[128];

// ---------------- u64-key top-k: key = monotonic(dist) << 32 | j -----------------
__device__ __forceinline__ unsigned long long fkey(float v, int j) {
    unsigned int b = __float_as_uint(v);
    b = (b & 0x80000000u) ? ~b : (b | 0x80000000u);   // total order on floats
    return ((unsigned long long)b << 32) | (unsigned int)j;
}

__device__ __forceinline__ void kinsert64(unsigned long long k,
                                          unsigned long long (&keys)[KNN]) {
    if (k < keys[KNN-1]) {
        int pos = KNN - 1;
#pragma unroll
        for (int t = KNN - 2; t >= 0; t--)
            if (k < keys[t]) pos = t;
#pragma unroll
        for (int t = KNN - 1; t >= 0; t--) {
            if (t > pos)       keys[t] = keys[t-1];
            else if (t == pos) keys[t] = k;
        }
    }
}

__device__ __forceinline__ void kmerge_write64(unsigned long long (&keys)[KNN], int row) {
    int lane = threadIdx.x & 31;
    for (int r = 0; r < KNN; r++) {
        unsigned long long ck = keys[0];
#pragma unroll
        for (int o = 16; o > 0; o >>= 1) {
            unsigned long long ok = __shfl_xor_sync(0xffffffffu, ck, o);
            if (ok < ck) ck = ok;
        }
        if (lane == 0) g_idx[row * KNN + r] = (int)(unsigned int)(ck & 0xFFFFFFFFull);
        if (keys[0] == ck) {
#pragma unroll
            for (int t = 0; t < KNN - 1; t++) keys[t] = keys[t+1];
            keys[KNN-1] = KEY_MAX;
        }
    }
}

// ---------------- knn1 fused: dist-on-the-fly + top-20 + ec1_pre ----------------
__global__ __launch_bounds__(512) void knn1_kernel(
    const float* __restrict__ pos, const float* __restrict__ W1a,
    const float* __restrict__ b1a) {
    __shared__ __align__(16) float4 sp[PTS];   // 16 KB: {x,y,z,d2}
    __shared__ float sw[384];
    __shared__ float sb[64];
    int cloud  = blockIdx.x >> 6;      // 64 blocks per cloud, 16 rows per block
    int rowblk = blockIdx.x & 63;
    const float* pb = pos + (size_t)cloud * PTS * 3;
    for (int p = threadIdx.x; p < PTS; p += 512) {
        float x = pb[p*3], y = pb[p*3+1], z = pb[p*3+2];
        float d2 = __fadd_rn(__fadd_rn(__fmul_rn(x,x), __fmul_rn(y,y)), __fmul_rn(z,z));
        sp[p] = make_float4(x, y, z, d2);
    }
    for (int t = threadIdx.x; t < 384; t += 512) sw[t] = W1a[t];
    if (threadIdx.x < 64) sb[threadIdx.x] = b1a[threadIdx.x];
    __syncthreads();

    int warp = threadIdx.x >> 5, lane = threadIdx.x & 31;
    int il = rowblk * 16 + warp;
    float4 q = sp[il];

    unsigned long long keys[KNN];
#pragma unroll
    for (int t = 0; t < KNN; t++) keys[t] = KEY_MAX;

    for (int t = 0; t < 32; t++) {
        int j = t * 32 + lane;
        float4 p = sp[j];
        float dot = __fadd_rn(__fadd_rn(__fmul_rn(q.x,p.x), __fmul_rn(q.y,p.y)), __fmul_rn(q.z,p.z));
        float v = __fsub_rn(__fadd_rn(q.w, p.w), __fmul_rn(2.0f, dot));
        kinsert64(fkey(v, j), keys);
    }
    kmerge_write64(keys, cloud * PTS + il);

    // fused ec1_pre: u = x@(A-B)+b1a, v = x@B for this block's 16 points
    int c = threadIdx.x & 63;
#pragma unroll
    for (int rep = 0; rep < 2; rep++) {
        int pl  = (threadIdx.x >> 6) + rep * 8;
        int il2 = rowblk * 16 + pl;
        float4 P = sp[il2];
        float a  = P.x * sw[c]       + P.y * sw[64 + c]  + P.z * sw[128 + c];
        float bb = P.x * sw[192 + c] + P.y * sw[256 + c] + P.z * sw[320 + c];
        int gp = ((cloud << 10) + il2) * 64 + c;
        g_u1[gp] = a - bb + sb[c];
        g_v1[gp] = bb;
    }
}

// ---------------- knn2 top-k (reads g_dist, float4 per lane) ---------------------
__global__ __launch_bounds__(256) void topk_kernel() {
    int warp = (blockIdx.x * blockDim.x + threadIdx.x) >> 5;
    int lane = threadIdx.x & 31;
    if (warp >= NPT) return;
    const float4* row = (const float4*)(g_dist + ((size_t)warp << 10));

    unsigned long long keys[KNN];
#pragma unroll
    for (int t = 0; t < KNN; t++) keys[t] = KEY_MAX;
#pragma unroll
    for (int t = 0; t < 8; t++) {
        int e = t * 32 + lane;
        float4 v = row[e];
        int j = e << 2;
        kinsert64(fkey(v.x, j),     keys);
        kinsert64(fkey(v.y, j + 1), keys);
        kinsert64(fkey(v.z, j + 2), keys);
        kinsert64(fkey(v.w, j + 3), keys);
    }
    kmerge_write64(keys, warp);
}

// ---------------- BN stats: per-point algebraic fold -----------------------------
__global__ __launch_bounds__(256) void ec1_stats_kernel() {
    int c  = threadIdx.x & 63;
    int sl = threadIdx.x >> 6;   // 0..3
    int p0 = blockIdx.x * 32;    // 1024 blocks x 32 points
    float s = 0.f, s2 = 0.f;
    for (int pp = sl; pp < 32; pp += 4) {
        int p = p0 + pp;
        int base = (p >> 10) << 10;
        float u = g_u1[p * 64 + c];
        int id[KNN];
#pragma unroll
        for (int k = 0; k < KNN; k++) id[k] = g_idx[p * KNN + k];
        float S = 0.f, T = 0.f;
#pragma unroll
        for (int k = 0; k < KNN; k++) {
            float v = g_v1[(base + id[k]) * 64 + c];
            S += v;
            T = fmaf(v, v, T);
        }
        s  += fmaf(20.0f, u, S);
        s2 += fmaf(u, fmaf(20.0f, u, 2.0f * S), T);
    }
    __shared__ float sh[2][4][64];
    sh[0][sl][c] = s; sh[1][sl][c] = s2;
    __syncthreads();
    if (sl == 0) {
        float ts = sh[0][0][c] + sh[0][1][c] + sh[0][2][c] + sh[0][3][c];
        float t2 = sh[1][0][c] + sh[1][1][c] + sh[1][2][c] + sh[1][3][c];
        g_part[blockIdx.x * 128 + c]      = ts;
        g_part[blockIdx.x * 128 + 64 + c] = t2;
    }
}

// ---------------- BN finalize (16-way partials) -----------------------------------
__global__ __launch_bounds__(1024) void ec1_bn_kernel(
    const float* __restrict__ g1, const float* __restrict__ be1) {
    int c = threadIdx.x & 63;
    int g = threadIdx.x >> 6;    // 0..15
    float s = 0.f, s2 = 0.f;
    for (int b = g; b < STATS_BLOCKS; b += 16) {
        s  += g_part[b * 128 + c];
        s2 += g_part[b * 128 + 64 + c];
    }
    __shared__ float sh[16][64], sh2[16][64];
    sh[g][c] = s; sh2[g][c] = s2;
    __syncthreads();
    if (g == 0) {
        float ts = 0.f, t2 = 0.f;
#pragma unroll
        for (int r = 0; r < 16; r++) { ts += sh[r][c]; t2 += sh2[r][c]; }
        float n   = (float)EDGES;
        float mu  = ts / n;
        float var = t2 / n - mu * mu;
        float sc  = g1[c] * rsqrtf(var + 1e-5f);
        g_scale[c] = sc;
        g_shift[c] = be1[c] - mu * sc;
    }
}

// ---------------- EdgeConv1 apply: micro-tiled GEMM (5k x 4c per thread) ---------
// Per point: H[20,64] @ W[64,64] -> max over k. Threads: 4 kg x 16 cg per point.
// sWt holds W transposed [c][d] with XOR quad swizzle (dq ^ cg) for conflict-free
// unique-lane reads. d-pairs ride in f32x2 lanes -> no packing MOVs.
__global__ __launch_bounds__(256) void ec1_apply_kernel(
    const float* __restrict__ W1b, const float* __restrict__ b1b) {
    int tid = threadIdx.x;
    int pt  = tid >> 6;          // 4 points per block
    int t64 = tid & 63;
    int i   = blockIdx.x * 4 + pt;
    int kg  = t64 >> 4;          // 0..3
    int cg  = t64 & 15;          // 0..15

    __shared__ __align__(16) float hb[4][KNN][64];   // 20 KB
    __shared__ __align__(16) float sWt[64][64];      // 16 KB, swizzled transpose
    __shared__ __align__(16) float red[4][4][16][4]; // 4 KB
    __shared__ float npart[4][16];

    // stage W transposed + swizzled: sWt[c][ ((dq ^ (c>>2)) << 2) + dd ] = W[d][c]
    for (int l = tid; l < 4096; l += 256) {
        int d = l >> 6, c = l & 63;
        int e = (((d >> 2) ^ (c >> 2)) << 2) + (d & 3);
        sWt[c][e] = W1b[l];
    }

    // stage relu'd edges (channel = t64)
    {
        int c = t64;
        float sc  = g_scale[c], shv = g_shift[c];
        float a   = fmaf(g_u1[i * 64 + c], sc, shv);
        int  base = (i >> 10) << 10;
        int id[KNN];
#pragma unroll
        for (int k = 0; k < KNN; k++) id[k] = g_idx[i * KNN + k];
#pragma unroll
        for (int k = 0; k < KNN; k++)
            hb[pt][k][c] = fmaxf(fmaf(g_v1[(base + id[k]) * 64 + c], sc, a), 0.0f);
    }
    __syncthreads();

    // GEMM: acc[q][cc] accumulates d-pair lanes (even d, odd d)
    unsigned long long acc[5][4];
#pragma unroll
    for (int q = 0; q < 5; q++)
#pragma unroll
        for (int cc = 0; cc < 4; cc++) acc[q][cc] = 0ull;

#pragma unroll
    for (int dq = 0; dq < 16; dq++) {
        int e = (dq ^ cg) << 2;
        ulonglong2 w0 = *(const ulonglong2*)&sWt[4*cg + 0][e];
        ulonglong2 w1 = *(const ulonglong2*)&sWt[4*cg + 1][e];
        ulonglong2 w2_ = *(const ulonglong2*)&sWt[4*cg + 2][e];
        ulonglong2 w3 = *(const ulonglong2*)&sWt[4*cg + 3][e];
#pragma unroll
        for (int q = 0; q < 5; q++) {
            ulonglong2 h = *(const ulonglong2*)&hb[pt][kg*5 + q][dq << 2];
            fma2(acc[q][0], h.x, w0.x); fma2(acc[q][0], h.y, w0.y);
            fma2(acc[q][1], h.x, w1.x); fma2(acc[q][1], h.y, w1.y);
            fma2(acc[q][2], h.x, w2_.x); fma2(acc[q][2], h.y, w2_.y);
            fma2(acc[q][3], h.x, w3.x); fma2(acc[q][3], h.y, w3.y);
        }
    }

    // per-thread max over 5 k
    float m0 = -FLT_MAX, m1 = -FLT_MAX, m2 = -FLT_MAX, m3 = -FLT_MAX;
#pragma unroll
    for (int q = 0; q < 5; q++) {
        float2 a0 = upk2(acc[q][0]);
        float2 a1 = upk2(acc[q][1]);
        float2 a2 = upk2(acc[q][2]);
        float2 a3 = upk2(acc[q][3]);
        m0 = fmaxf(m0, a0.x + a0.y);
        m1 = fmaxf(m1, a1.x + a1.y);
        m2 = fmaxf(m2, a2.x + a2.y);
        m3 = fmaxf(m3, a3.x + a3.y);
    }
    *(float4*)&red[pt][kg][cg][0] = make_float4(m0, m1, m2, m3);
    __syncthreads();

    if (kg == 0) {
        float4 r0 = *(const float4*)&red[pt][0][cg][0];
        float4 r1 = *(const float4*)&red[pt][1][cg][0];
        float4 r2 = *(const float4*)&red[pt][2][cg][0];
        float4 r3 = *(const float4*)&red[pt][3][cg][0];
        float4 b4 = *(const float4*)&b1b[4*cg];
        float4 o;
        o.x = fmaxf(fmaxf(r0.x, r1.x), fmaxf(r2.x, r3.x)) + b4.x;
        o.y = fmaxf(fmaxf(r0.y, r1.y), fmaxf(r2.y, r3.y)) + b4.y;
        o.z = fmaxf(fmaxf(r0.z, r1.z), fmaxf(r2.z, r3.z)) + b4.z;
        o.w = fmaxf(fmaxf(r0.w, r1.w), fmaxf(r2.w, r3.w)) + b4.w;
        *(float4*)&g_x1[i * 64 + 4*cg] = o;
        npart[pt][cg] = ((o.x * o.x + o.y * o.y) + (o.z * o.z + o.w * o.w));
    }
    __syncthreads();
    if (t64 == 0) {
        float s = 0.f;
#pragma unroll
        for (int m = 0; m < 16; m++) s += npart[pt][m];
        g_n2[i] = s;
    }
}

// ---------------- knn2: Gram GEMM, 128x128 tile / 8x8 microtile, f32x2 -----------
__global__ __launch_bounds__(256) void gram_kernel() {
    int b  = blockIdx.z;
    int i0 = blockIdx.y << 7;
    int j0 = blockIdx.x << 7;
    const float* xb = g_x1 + ((size_t)b << 10) * 64;

    __shared__ __align__(16) float As[16][132];
    __shared__ __align__(16) float Bs[16][132];

    int tid = threadIdx.x;
    int tx = tid & 15, ty = tid >> 4;
    int lr = tid >> 2, lc4 = tid & 3;

    unsigned long long ACC[8][4];   // packed pairs over s
#pragma unroll
    for (int r = 0; r < 8; r++)
#pragma unroll
        for (int s = 0; s < 4; s++) ACC[r][s] = 0ull;

    for (int k0 = 0; k0 < 64; k0 += 16) {
#pragma unroll
        for (int half = 0; half < 2; half++) {
            int r = lr + half * 64;
            float4 av = *(const float4*)&xb[(i0 + r) * 64 + k0 + lc4 * 4];
            float4 bv = *(const float4*)&xb[(j0 + r) * 64 + k0 + lc4 * 4];
            As[lc4*4+0][r] = av.x; As[lc4*4+1][r] = av.y;
            As[lc4*4+2][r] = av.z; As[lc4*4+3][r] = av.w;
            Bs[lc4*4+0][r] = bv.x; Bs[lc4*4+1][r] = bv.y;
            Bs[lc4*4+2][r] = bv.z; Bs[lc4*4+3][r] = bv.w;
        }
        __syncthreads();
#pragma unroll
        for (int k = 0; k < 16; k++) {
            float4 a0 = *(const float4*)&As[k][ty << 3];
            float4 a1 = *(const float4*)&As[k][(ty << 3) + 4];
            ulonglong2 B0 = *(const ulonglong2*)&Bs[k][tx << 3];
            ulonglong2 B1 = *(const ulonglong2*)&Bs[k][(tx << 3) + 4];
            unsigned long long A[8];
            A[0] = pk2(a0.x, a0.x); A[1] = pk2(a0.y, a0.y);
            A[2] = pk2(a0.z, a0.z); A[3] = pk2(a0.w, a0.w);
            A[4] = pk2(a1.x, a1.x); A[5] = pk2(a1.y, a1.y);
            A[6] = pk2(a1.z, a1.z); A[7] = pk2(a1.w, a1.w);
#pragma unroll
            for (int r = 0; r < 8; r++) {
                fma2(ACC[r][0], A[r], B0.x);
                fma2(ACC[r][1], A[r], B0.y);
                fma2(ACC[r][2], A[r], B1.x);
                fma2(ACC[r][3], A[r], B1.y);
            }
        }
        __syncthreads();
    }

    float nj[8];
#pragma unroll
    for (int s = 0; s < 8; s++) nj[s] = g_n2[(b << 10) + j0 + (tx << 3) + s];
#pragma unroll
    for (int r = 0; r < 8; r++) {
        int i = i0 + (ty << 3) + r;
        float ni = g_n2[(b << 10) + i];
        float2 c0 = upk2(ACC[r][0]), c1 = upk2(ACC[r][1]);
        float2 c2 = upk2(ACC[r][2]), c3 = upk2(ACC[r][3]);
        float4 o0, o1;
        o0.x = __fsub_rn(__fadd_rn(ni, nj[0]), __fmul_rn(2.0f, c0.x));
        o0.y = __fsub_rn(__fadd_rn(ni, nj[1]), __fmul_rn(2.0f, c0.y));
        o0.z = __fsub_rn(__fadd_rn(ni, nj[2]), __fmul_rn(2.0f, c1.x));
        o0.w = __fsub_rn(__fadd_rn(ni, nj[3]), __fmul_rn(2.0f, c1.y));
        o1.x = __fsub_rn(__fadd_rn(ni, nj[4]), __fmul_rn(2.0f, c2.x));
        o1.y = __fsub_rn(__fadd_rn(ni, nj[5]), __fmul_rn(2.0f, c2.y));
        o1.z = __fsub_rn(__fadd_rn(ni, nj[6]), __fmul_rn(2.0f, c3.x));
        o1.w = __fsub_rn(__fadd_rn(ni, nj[7]), __fmul_rn(2.0f, c3.y));
        size_t off = ((size_t)b << 20) + ((size_t)i << 10) + j0 + (tx << 3);
        *(float4*)&g_dist[off]     = o0;
        *(float4*)&g_dist[off + 4] = o1;
    }
}

// ---------------- Weff = WlA + (A-B)@WlB ; beff = b2@WlB -------------------------
__global__ __launch_bounds__(128) void prep_weff_kernel(
    const float* __restrict__ W2, const float* __restrict__ b2,
    const float* __restrict__ Wl) {
    int c = threadIdx.x;
    if (blockIdx.x < 64) {
        int d = blockIdx.x;
        float a0 = 0.f, a1 = 0.f, a2 = 0.f, a3 = 0.f;
        for (int e = 0; e < 128; e += 4) {
            a0 = fmaf(W2[d*128+e]   - W2[(64+d)*128+e],   Wl[(64+e)*128+c],   a0);
            a1 = fmaf(W2[d*128+e+1] - W2[(64+d)*128+e+1], Wl[(64+e+1)*128+c], a1);
            a2 = fmaf(W2[d*128+e+2] - W2[(64+d)*128+e+2], Wl[(64+e+2)*128+c], a2);
            a3 = fmaf(W2[d*128+e+3] - W2[(64+d)*128+e+3], Wl[(64+e+3)*128+c], a3);
        }
        g_Weff[d * 128 + c] = Wl[d * 128 + c] + ((a0 + a1) + (a2 + a3));
    } else {
        float a0 = 0.f, a1 = 0.f;
        for (int e = 0; e < 128; e += 2) {
            a0 = fmaf(b2[e],     Wl[(64+e)*128+c],   a0);
            a1 = fmaf(b2[e+1],   Wl[(64+e+1)*128+c], a1);
        }
        g_beff[c] = a0 + a1;
    }
}

// ---------------- EdgeConv2 v-branch: v2 = x1 @ W2[64:128], f32x2 ----------------
__global__ __launch_bounds__(256) void ec2_pre_kernel(const float* __restrict__ W2) {
    int c  = threadIdx.x & 127;
    int pg = threadIdx.x >> 7;   // 0 or 1
    unsigned long long w2[32];
#pragma unroll
    for (int d = 0; d < 32; d++)
        w2[d] = pk2(W2[(64 + 2*d) * 128 + c], W2[(64 + 2*d+1) * 128 + c]);

    __shared__ __align__(16) float xs[8][64];
    int p0 = blockIdx.x * 128;
    for (int r = 0; r < 16; r++) {
        int pb = p0 + r * 8;
#pragma unroll
        for (int s = 0; s < 2; s++) {
            int q = threadIdx.x + s * 256;
            xs[q >> 6][q & 63] = g_x1[(size_t)(pb + (q >> 6)) * 64 + (q & 63)];
        }
        __syncthreads();
#pragma unroll
        for (int pp = 0; pp < 4; pp++) {
            int p = pg + pp * 2;
            unsigned long long Y0 = 0ull, Y1 = 0ull, Y2 = 0ull, Y3 = 0ull;
            const ulonglong2* xp = (const ulonglong2*)&xs[p][0];
#pragma unroll
            for (int i4 = 0; i4 < 16; i4 += 4) {
                ulonglong2 q0 = xp[i4];
                ulonglong2 q1 = xp[i4 + 1];
                ulonglong2 q2 = xp[i4 + 2];
                ulonglong2 q3 = xp[i4 + 3];
                fma2(Y0, q0.x, w2[2*i4]);     fma2(Y1, q0.y, w2[2*i4 + 1]);
                fma2(Y2, q1.x, w2[2*i4 + 2]); fma2(Y3, q1.y, w2[2*i4 + 3]);
                fma2(Y0, q2.x, w2[2*i4 + 4]); fma2(Y1, q2.y, w2[2*i4 + 5]);
                fma2(Y2, q3.x, w2[2*i4 + 6]); fma2(Y3, q3.y, w2[2*i4 + 7]);
            }
            float2 f0 = upk2(Y0), f1 = upk2(Y1), f2 = upk2(Y2), f3 = upk2(Y3);
            g_v2[(size_t)(pb + p) * 128 + c] =
                ((f0.x + f0.y) + (f1.x + f1.y)) + ((f2.x + f2.y) + (f3.x + f3.y));
        }
        __syncthreads();
    }
}

// ---------------- EdgeConv2 neighbor max: m = max_k v2[nbr] (float4) -------------
__global__ __launch_bounds__(256) void ec2_combine_kernel() {
    int t = blockIdx.x * 256 + threadIdx.x;   // NPT*32 threads
    int i  = t >> 5;
    int c4 = (t & 31) << 2;
    int base = (i >> 10) << 10;
    int id[KNN];
#pragma unroll
    for (int k = 0; k < KNN; k++) id[k] = g_idx[i * KNN + k];
    float4 m = make_float4(-FLT_MAX, -FLT_MAX, -FLT_MAX, -FLT_MAX);
#pragma unroll
    for (int k = 0; k < KNN; k++) {
        float4 v = *(const float4*)&g_v2[(size_t)(base + id[k]) * 128 + c4];
        m.x = fmaxf(m.x, v.x); m.y = fmaxf(m.y, v.y);
        m.z = fmaxf(m.z, v.z); m.w = fmaxf(m.w, v.w);
    }
    *(float4*)&g_m[(size_t)i * 128 + c4] = m;
}

// ---------------- fused final linear + running global max pool, f32x2 ------------
__global__ __launch_bounds__(384) void finpool_kernel(const float* __restrict__ Wl) {
    int tid = threadIdx.x;
    int g = tid / 128;       // 0,1,2 (k-chunk group)
    int c = tid % 128;

    unsigned long long w2[32];
    if (g == 0) {
#pragma unroll
        for (int d = 0; d < 32; d++)
            w2[d] = pk2(g_Weff[(2*d) * 128 + c], g_Weff[(2*d+1) * 128 + c]);
    } else if (g == 1) {
#pragma unroll
        for (int d = 0; d < 32; d++)
            w2[d] = pk2(Wl[(64 + 2*d) * 128 + c], Wl[(64 + 2*d+1) * 128 + c]);
    } else {
#pragma unroll
        for (int d = 0; d < 32; d++)
            w2[d] = pk2(Wl[(128 + 2*d) * 128 + c], Wl[(128 + 2*d+1) * 128 + c]);
    }
    int off = (g == 0) ? 0 : ((g == 1) ? 64 : 128);

    __shared__ __align__(16) float xs[4][192];
    __shared__ float ps[3][4][128];
    float rm = -FLT_MAX;
    int p0 = blockIdx.x * 256;

    for (int r = 0; r < 64; r++) {
        int pb = p0 + r * 4;
#pragma unroll
        for (int s = 0; s < 2; s++) {
            int q = tid + s * 384;
            int p = q / 192, e = q % 192;
            xs[p][e] = (e < 64) ? g_x1[(size_t)(pb + p) * 64 + e]
                                : g_m[(size_t)(pb + p) * 128 + (e - 64)];
        }
        __syncthreads();
#pragma unroll
        for (int p = 0; p < 4; p++) {
            unsigned long long Y0 = 0ull, Y1 = 0ull, Y2 = 0ull, Y3 = 0ull;
            const ulonglong2* xp = (const ulonglong2*)&xs[p][off];
#pragma unroll
            for (int i4 = 0; i4 < 16; i4 += 4) {
                ulonglong2 q0 = xp[i4];
                ulonglong2 q1 = xp[i4 + 1];
                ulonglong2 q2 = xp[i4 + 2];
                ulonglong2 q3 = xp[i4 + 3];
                fma2(Y0, q0.x, w2[2*i4]);     fma2(Y1, q0.y, w2[2*i4 + 1]);
                fma2(Y2, q1.x, w2[2*i4 + 2]); fma2(Y3, q1.y, w2[2*i4 + 3]);
                fma2(Y0, q2.x, w2[2*i4 + 4]); fma2(Y1, q2.y, w2[2*i4 + 5]);
                fma2(Y2, q3.x, w2[2*i4 + 6]); fma2(Y3, q3.y, w2[2*i4 + 7]);
            }
            float2 f0 = upk2(Y0), f1 = upk2(Y1), f2 = upk2(Y2), f3 = upk2(Y3);
            ps[g][p][c] = ((f0.x + f0.y) + (f1.x + f1.y)) + ((f2.x + f2.y) + (f3.x + f3.y));
        }
        __syncthreads();
        if (g == 0) {
#pragma unroll
            for (int p = 0; p < 4; p++)
                rm = fmaxf(rm, ps[0][p][c] + ps[1][p][c] + ps[2][p][c]);
        }
    }
    if (g == 0) g_part[blockIdx.x * 128 + c] = rm;
}

// ---------------- final reduce over 4 segments per cloud -------------------------
__global__ void pool2_kernel(const float* __restrict__ bl, float* __restrict__ out) {
    int b = blockIdx.x;       // 32
    int c = threadIdx.x;      // 128
    float m = -FLT_MAX;
#pragma unroll
    for (int s = 0; s < 4; s++) m = fmaxf(m, g_part[(b * 4 + s) * 128 + c]);
    out[b * 128 + c] = m + g_beff[c] + bl[c];
}

// ---------------- launch --------------------------------------------------------
extern "C" void kernel_launch(void* const* d_in, const int* in_sizes, int n_in,
                              void* d_out, int out_size) {
    const float* pos = (const float*)d_in[0];
    const float* W1a = (const float*)d_in[1];
    const float* b1a = (const float*)d_in[2];
    const float* g1  = (const float*)d_in[3];
    const float* be1 = (const float*)d_in[4];
    const float* W1b = (const float*)d_in[5];
    const float* b1b = (const float*)d_in[6];
    const float* W2  = (const float*)d_in[7];
    const float* b2  = (const float*)d_in[8];
    const float* Wl  = (const float*)d_in[9];
    const float* bl  = (const float*)d_in[10];
    float* out = (float*)d_out;

    // knn on pos (fused dist + top-k + ec1_pre)
    knn1_kernel<<<2048, 512>>>(pos, W1a, b1a);

    // EdgeConv1 — ec1_apply deliberately kept as the 4th launch (ncu captures #4)
    ec1_stats_kernel<<<STATS_BLOCKS, 256>>>();
    ec1_bn_kernel<<<1, 1024>>>(g1, be1);
    ec1_apply_kernel<<<NPT / 4, 256>>>(W1b, b1b);   // + fused n2

    prep_weff_kernel<<<65, 128>>>(W2, b2, Wl);      // independent of point data

    // knn on x1
    gram_kernel<<<dim3(8, 8, BATCH), 256>>>();
    topk_kernel<<<NPT / 8, 256>>>();

    // EdgeConv2 (v-branch only; u-branch folded into Weff)
    ec2_pre_kernel<<<256, 256>>>(W2);
    ec2_combine_kernel<<<NPT * 32 / 256, 256>>>();

    // fused final linear + pool
    finpool_kernel<<<128, 384>>>(Wl);
    pool2_kernel<<<BATCH, 128>>>(bl, out);
}